// round 1
// baseline (speedup 1.0000x reference)
#include <cuda_runtime.h>

#define B_  16
#define C_  64
#define O_  64
#define H_  64
#define Wd_ 64
#define HW_ (H_ * Wd_)
#define EPSF 1e-6f
#define SLOPE 0.01f

// ---- scratch (device globals; no allocations allowed) ----
__device__ float g_cmax0[B_ * HW_];
__device__ float g_cmin0[B_ * HW_];
__device__ float g_cmax1[B_ * HW_];
__device__ float g_cmin1[B_ * HW_];
__device__ float g_s0[B_ * HW_];   // (max-min)+eps for even parity
__device__ float g_s1[B_ * HW_];   // (max-min)+eps for odd parity

// ------------------------------------------------------------------
// Kernel 1: per-pixel channel reduce (max/min over channels, split by parity)
// one thread per (b, h, w); coalesced over w.
// ------------------------------------------------------------------
__global__ void chan_reduce_kernel(const float* __restrict__ x) {
    int t = blockIdx.x * blockDim.x + threadIdx.x;       // 0 .. 65535
    int b  = t >> 12;
    int hw = t & (HW_ - 1);
    const float* xb = x + (size_t)b * C_ * HW_ + hw;

    float mx0 = -1e30f, mn0 = 1e30f;
    float mx1 = -1e30f, mn1 = 1e30f;
#pragma unroll 8
    for (int c = 0; c < C_; c += 2) {
        float v0 = xb[(size_t)c * HW_];
        float v1 = xb[(size_t)(c + 1) * HW_];
        mx0 = fmaxf(mx0, v0); mn0 = fminf(mn0, v0);
        mx1 = fmaxf(mx1, v1); mn1 = fminf(mn1, v1);
    }
    g_cmax0[t] = mx0; g_cmin0[t] = mn0;
    g_cmax1[t] = mx1; g_cmin1[t] = mn1;
}

// ------------------------------------------------------------------
// Kernel 2: 3x3 window (replicate clamp) over channel-reduced max/min,
// producing s = (max - min) + eps per parity.
// ------------------------------------------------------------------
__global__ void window_std_kernel() {
    int t = blockIdx.x * blockDim.x + threadIdx.x;       // 0 .. 65535
    int b = t >> 12;
    int h = (t >> 6) & 63;
    int w = t & 63;
    int base = b * HW_;

    float mx0 = -1e30f, mn0 = 1e30f;
    float mx1 = -1e30f, mn1 = 1e30f;
#pragma unroll
    for (int di = -1; di <= 1; di++) {
#pragma unroll
        for (int dj = -1; dj <= 1; dj++) {
            int hh = min(max(h + di, 0), 63);
            int ww = min(max(w + dj, 0), 63);
            int idx = base + hh * 64 + ww;
            mx0 = fmaxf(mx0, g_cmax0[idx]); mn0 = fminf(mn0, g_cmin0[idx]);
            mx1 = fmaxf(mx1, g_cmax1[idx]); mn1 = fminf(mn1, g_cmin1[idx]);
        }
    }
    g_s0[t] = (mx0 - mn0) + EPSF;
    g_s1[t] = (mx1 - mn1) + EPSF;
}

// ------------------------------------------------------------------
// Kernel 3: main conv.
// Block: 8x8 pixel tile of one batch, all 64 output channels.
// 256 threads = 16 pixel-quads (2x2 each) x 16 o-groups (4 O each).
// Each thread keeps accE[4 o][4 px], accO[4 o][4 px] (parity-split sums).
// ------------------------------------------------------------------
#define TS 8            // output tile side
#define XS_W 10         // padded tile side
#define CCHUNK 32       // channels per weight smem chunk

__device__ __forceinline__ void do_channel(const float* __restrict__ xr,
                                           const float* __restrict__ wrow,
                                           float (&acc)[16]) {
    // load 4x4 input patch for the 2x2 pixel quad
    float xv[16];
#pragma unroll
    for (int i = 0; i < 4; i++)
#pragma unroll
        for (int j = 0; j < 4; j++)
            xv[i * 4 + j] = xr[i * XS_W + j];

#pragma unroll
    for (int oo = 0; oo < 4; oo++) {
#pragma unroll
        for (int tp = 0; tp < 9; tp++) {
            const int i = tp / 3, j = tp % 3;
            float wv = wrow[oo * 9 + tp];
            acc[oo * 4 + 0] = fmaf(xv[(i    ) * 4 + j    ], wv, acc[oo * 4 + 0]);
            acc[oo * 4 + 1] = fmaf(xv[(i    ) * 4 + j + 1], wv, acc[oo * 4 + 1]);
            acc[oo * 4 + 2] = fmaf(xv[(i + 1) * 4 + j    ], wv, acc[oo * 4 + 2]);
            acc[oo * 4 + 3] = fmaf(xv[(i + 1) * 4 + j + 1], wv, acc[oo * 4 + 3]);
        }
    }
}

__global__ void conv_main_kernel(const float* __restrict__ x,
                                 const float* __restrict__ Wt,
                                 const float* __restrict__ bias,
                                 float* __restrict__ out) {
    extern __shared__ float sm[];
    float* xs = sm;                       // [64][10*10] = 6400 floats
    float* ws = sm + C_ * (XS_W * XS_W);  // [CCHUNK][64][9] = 18432 floats

    const int b  = blockIdx.z;
    const int h0 = blockIdx.y * TS;
    const int w0 = blockIdx.x * TS;
    const int tid = threadIdx.x;

    // ---- load input tile (replicate-clamped 10x10, all 64 channels) ----
    const float* xb = x + (size_t)b * C_ * HW_;
    for (int idx = tid; idx < C_ * XS_W * XS_W; idx += 256) {
        int c   = idx / (XS_W * XS_W);
        int pos = idx % (XS_W * XS_W);
        int r  = pos / XS_W;
        int cl = pos % XS_W;
        int gh = min(max(h0 + r  - 1, 0), 63);
        int gw = min(max(w0 + cl - 1, 0), 63);
        xs[idx] = xb[(size_t)c * HW_ + gh * 64 + gw];
    }

    // thread mapping
    const int po = tid & 15;          // pixel-quad id
    const int og = tid >> 4;          // o-group id
    const int ph = (po >> 2) * 2;     // quad top row within tile
    const int pw = (po & 3) * 2;      // quad left col within tile
    const int obase = og * 4;

    float accE[16], accO[16];
#pragma unroll
    for (int i = 0; i < 16; i++) { accE[i] = 0.f; accO[i] = 0.f; }

    for (int cc = 0; cc < C_; cc += CCHUNK) {
        __syncthreads();   // protect ws from previous chunk's readers
        // load weight chunk: ws[c'][o][t], t = i*3+j maps to W[o][cc+c'][j][i]
        for (int idx = tid; idx < CCHUNK * O_ * 9; idx += 256) {
            int c  = idx / (O_ * 9);
            int r  = idx % (O_ * 9);
            int o  = r / 9;
            int t9 = r % 9;
            int i  = t9 / 3, j = t9 % 3;
            ws[idx] = Wt[(size_t)o * (C_ * 9) + (cc + c) * 9 + j * 3 + i];
        }
        __syncthreads();

        const float* xbase = &xs[ph * XS_W + pw];
#pragma unroll 2
        for (int c2 = 0; c2 < CCHUNK; c2 += 2) {
            do_channel(xbase + (cc + c2    ) * (XS_W * XS_W),
                       &ws[(c2    ) * (O_ * 9) + obase * 9], accE);
            do_channel(xbase + (cc + c2 + 1) * (XS_W * XS_W),
                       &ws[(c2 + 1) * (O_ * 9) + obase * 9], accO);
        }
    }

    // ---- epilogue: combine parities, bias, leaky relu, rescale ----
    const int bHW = b * HW_;
#pragma unroll
    for (int pi = 0; pi < 2; pi++) {
#pragma unroll
        for (int pj = 0; pj < 2; pj++) {
            int h = h0 + ph + pi;
            int w = w0 + pw + pj;
            int sidx = bHW + h * 64 + w;
            float s0e = g_s0[sidx];
            float s1e = g_s1[sidx];
            float inv0 = 1.0f / s0e;
            float inv1 = 1.0f / s1e;
            int px = pi * 2 + pj;
#pragma unroll
            for (int oo = 0; oo < 4; oo++) {
                int o = obase + oo;
                float v = accE[oo * 4 + px] * inv0
                        + accO[oo * 4 + px] * inv1
                        + bias[o];
                v = (v >= 0.f) ? v : (SLOPE * v);
                v *= (o & 1) ? s1e : s0e;
                out[((size_t)(b * O_ + o) * H_ + h) * Wd_ + w] = v;
            }
        }
    }
}

// ------------------------------------------------------------------
extern "C" void kernel_launch(void* const* d_in, const int* in_sizes, int n_in,
                              void* d_out, int out_size) {
    const float* x    = (const float*)d_in[0];   // [16,64,64,64]
    const float* Wt   = (const float*)d_in[1];   // [64,64,3,3]
    const float* bias = (const float*)d_in[2];   // [64]
    float* out = (float*)d_out;

    const int smem_bytes = (C_ * XS_W * XS_W + CCHUNK * O_ * 9) * sizeof(float);
    cudaFuncSetAttribute(conv_main_kernel,
                         cudaFuncAttributeMaxDynamicSharedMemorySize, smem_bytes);

    chan_reduce_kernel<<<(B_ * HW_) / 256, 256>>>(x);
    window_std_kernel<<<(B_ * HW_) / 256, 256>>>();

    dim3 grid(Wd_ / TS, H_ / TS, B_);   // (8, 8, 16)
    conv_main_kernel<<<grid, 256, smem_bytes>>>(x, Wt, bias, out);
}

// round 2
// speedup vs baseline: 1.1521x; 1.1521x over previous
#include <cuda_runtime.h>

#define B_  16
#define C_  64
#define O_  64
#define H_  64
#define Wd_ 64
#define HW_ (H_ * Wd_)
#define EPSF 1e-6f
#define SLOPE 0.01f

typedef unsigned long long ull;

// ---- scratch (device globals; no allocations allowed) ----
__device__ float g_cmax0[B_ * HW_];
__device__ float g_cmin0[B_ * HW_];
__device__ float g_cmax1[B_ * HW_];
__device__ float g_cmin1[B_ * HW_];
__device__ float g_s0[B_ * HW_];   // (max-min)+eps for even parity
__device__ float g_s1[B_ * HW_];   // (max-min)+eps for odd parity

// ------------------------------------------------------------------
// Kernel 1: per-pixel channel reduce (max/min over channels, by parity)
// ------------------------------------------------------------------
__global__ void chan_reduce_kernel(const float* __restrict__ x) {
    int t = blockIdx.x * blockDim.x + threadIdx.x;       // 0 .. 65535
    int b  = t >> 12;
    int hw = t & (HW_ - 1);
    const float* xb = x + (size_t)b * C_ * HW_ + hw;

    float mx0 = -1e30f, mn0 = 1e30f;
    float mx1 = -1e30f, mn1 = 1e30f;
#pragma unroll 8
    for (int c = 0; c < C_; c += 2) {
        float v0 = xb[(size_t)c * HW_];
        float v1 = xb[(size_t)(c + 1) * HW_];
        mx0 = fmaxf(mx0, v0); mn0 = fminf(mn0, v0);
        mx1 = fmaxf(mx1, v1); mn1 = fminf(mn1, v1);
    }
    g_cmax0[t] = mx0; g_cmin0[t] = mn0;
    g_cmax1[t] = mx1; g_cmin1[t] = mn1;
}

// ------------------------------------------------------------------
// Kernel 2: 3x3 replicate-clamped window range -> s = (max-min)+eps
// ------------------------------------------------------------------
__global__ void window_std_kernel() {
    int t = blockIdx.x * blockDim.x + threadIdx.x;       // 0 .. 65535
    int b = t >> 12;
    int h = (t >> 6) & 63;
    int w = t & 63;
    int base = b * HW_;

    float mx0 = -1e30f, mn0 = 1e30f;
    float mx1 = -1e30f, mn1 = 1e30f;
#pragma unroll
    for (int di = -1; di <= 1; di++) {
#pragma unroll
        for (int dj = -1; dj <= 1; dj++) {
            int hh = min(max(h + di, 0), 63);
            int ww = min(max(w + dj, 0), 63);
            int idx = base + hh * 64 + ww;
            mx0 = fmaxf(mx0, g_cmax0[idx]); mn0 = fminf(mn0, g_cmin0[idx]);
            mx1 = fmaxf(mx1, g_cmax1[idx]); mn1 = fminf(mn1, g_cmin1[idx]);
        }
    }
    g_s0[t] = (mx0 - mn0) + EPSF;
    g_s1[t] = (mx1 - mn1) + EPSF;
}

// ------------------------------------------------------------------
// Kernel 3: main conv with packed f32x2 over channel parity.
// Block: 8x8 pixel tile of one batch, all 64 output channels.
// 256 threads = 16 pixel-quads (2x2) x 16 o-groups (4 O each).
// acc2[oo][px] packs (even-channel sum, odd-channel sum).
// smem: xs[cpair=32][100 pos][2 par], ws[cpair=16][64 o][9 tap][2 par]
// ------------------------------------------------------------------
#define TS 8            // output tile side
#define XS_W 10         // padded tile side
#define CPCHUNK 16      // channel-pairs per weight smem chunk (=32 channels)

__device__ __forceinline__ void ffma2(ull& d, ull a, ull b) {
    asm("fma.rn.f32x2 %0, %1, %2, %0;" : "+l"(d) : "l"(a), "l"(b));
}

__global__ void conv_main_kernel(const float* __restrict__ x,
                                 const float* __restrict__ Wt,
                                 const float* __restrict__ bias,
                                 float* __restrict__ out) {
    extern __shared__ float sm[];
    float* xs = sm;                                 // 32 pairs * 100 * 2 = 6400 floats
    float* ws = sm + (C_ / 2) * (XS_W * XS_W) * 2;  // 16 * 64 * 9 * 2 = 18432 floats

    const int b  = blockIdx.z;
    const int h0 = blockIdx.y * TS;
    const int w0 = blockIdx.x * TS;
    const int tid = threadIdx.x;

    // ---- load input tile: replicate-clamped 10x10, parity-interleaved ----
    const float* xb = x + (size_t)b * C_ * HW_;
    for (int idx = tid; idx < C_ * XS_W * XS_W; idx += 256) {
        int c   = idx / (XS_W * XS_W);
        int pos = idx % (XS_W * XS_W);
        int r  = pos / XS_W;
        int cl = pos % XS_W;
        int gh = min(max(h0 + r  - 1, 0), 63);
        int gw = min(max(w0 + cl - 1, 0), 63);
        // xs[(cpair*100 + pos)*2 + parity]
        xs[(((c >> 1) * (XS_W * XS_W)) + pos) * 2 + (c & 1)] =
            xb[(size_t)c * HW_ + gh * 64 + gw];
    }

    // thread mapping
    const int po = tid & 15;          // pixel-quad id
    const int og = tid >> 4;          // o-group id
    const int ph = (po >> 2) * 2;     // quad top row within tile
    const int pw = (po & 3) * 2;      // quad left col within tile
    const int obase = og * 4;

    ull acc2[16];
#pragma unroll
    for (int i = 0; i < 16; i++) acc2[i] = 0ull;

    for (int cc = 0; cc < C_ / 2; cc += CPCHUNK) {
        __syncthreads();   // protect ws from previous chunk's readers
        // stage weights: ws[((cp*64 + o)*9 + t)*2 + par] = W[o][2*(cc+cp)+par][j][i]
        for (int idx = tid; idx < CPCHUNK * O_ * 9 * 2; idx += 256) {
            int par = idx & 1;
            int r   = idx >> 1;
            int t9  = r % 9;
            int o   = (r / 9) % O_;
            int cp  = r / (9 * O_);
            int i = t9 / 3, j = t9 % 3;
            ws[idx] = Wt[(size_t)o * (C_ * 9) + (2 * (cc + cp) + par) * 9 + j * 3 + i];
        }
        __syncthreads();

#pragma unroll 1
        for (int cp = 0; cp < CPCHUNK; cp++) {
            const int cpg = cc + cp;   // global channel-pair
            // load 4x4 patch of pairs
            const float* xr = &xs[((cpg * (XS_W * XS_W)) + ph * XS_W + pw) * 2];
            ull xv[16];
#pragma unroll
            for (int i = 0; i < 4; i++)
#pragma unroll
                for (int j = 0; j < 4; j++)
                    xv[i * 4 + j] = *reinterpret_cast<const ull*>(xr + (i * XS_W + j) * 2);

            const float* wr = &ws[((cp * O_ + obase) * 9) * 2];
#pragma unroll
            for (int oo = 0; oo < 4; oo++) {
#pragma unroll
                for (int t9 = 0; t9 < 9; t9++) {
                    const int i = t9 / 3, j = t9 % 3;
                    ull wv = *reinterpret_cast<const ull*>(wr + (oo * 9 + t9) * 2);
                    ffma2(acc2[oo * 4 + 0], xv[(i    ) * 4 + j    ], wv);
                    ffma2(acc2[oo * 4 + 1], xv[(i    ) * 4 + j + 1], wv);
                    ffma2(acc2[oo * 4 + 2], xv[(i + 1) * 4 + j    ], wv);
                    ffma2(acc2[oo * 4 + 3], xv[(i + 1) * 4 + j + 1], wv);
                }
            }
        }
    }

    // ---- epilogue: combine parities, bias, leaky relu, rescale ----
    const int bHW = b * HW_;
#pragma unroll
    for (int pi = 0; pi < 2; pi++) {
#pragma unroll
        for (int pj = 0; pj < 2; pj++) {
            int h = h0 + ph + pi;
            int w = w0 + pw + pj;
            int sidx = bHW + h * 64 + w;
            float s0e = g_s0[sidx];
            float s1e = g_s1[sidx];
            float inv0 = 1.0f / s0e;
            float inv1 = 1.0f / s1e;
            int px = pi * 2 + pj;
#pragma unroll
            for (int oo = 0; oo < 4; oo++) {
                int o = obase + oo;
                float aE, aO;
                asm("mov.b64 {%0, %1}, %2;" : "=f"(aE), "=f"(aO) : "l"(acc2[oo * 4 + px]));
                float v = aE * inv0 + aO * inv1 + bias[o];
                v = (v >= 0.f) ? v : (SLOPE * v);
                v *= (o & 1) ? s1e : s0e;
                out[((size_t)(b * O_ + o) * H_ + h) * Wd_ + w] = v;
            }
        }
    }
}

// ------------------------------------------------------------------
extern "C" void kernel_launch(void* const* d_in, const int* in_sizes, int n_in,
                              void* d_out, int out_size) {
    const float* x    = (const float*)d_in[0];   // [16,64,64,64]
    const float* Wt   = (const float*)d_in[1];   // [64,64,3,3]
    const float* bias = (const float*)d_in[2];   // [64]
    float* out = (float*)d_out;

    const int smem_bytes =
        ((C_ / 2) * (XS_W * XS_W) * 2 + CPCHUNK * O_ * 9 * 2) * sizeof(float);
    cudaFuncSetAttribute(conv_main_kernel,
                         cudaFuncAttributeMaxDynamicSharedMemorySize, smem_bytes);

    chan_reduce_kernel<<<(B_ * HW_) / 256, 256>>>(x);
    window_std_kernel<<<(B_ * HW_) / 256, 256>>>();

    dim3 grid(Wd_ / TS, H_ / TS, B_);   // (8, 8, 16)
    conv_main_kernel<<<grid, 256, smem_bytes>>>(x, Wt, bias, out);
}

// round 5
// speedup vs baseline: 2.0746x; 1.8007x over previous
#include <cuda_runtime.h>
#include <cuda_bf16.h>
#include <cstdint>

#define B_  16
#define C_  64
#define O_  64
#define H_  64
#define Wd_ 64
#define HW_ (H_ * Wd_)
#define EPSF 1e-6f
#define SLOPE 0.01f

// ---- scratch ----
__device__ float g_cmax0[B_ * HW_];
__device__ float g_cmin0[B_ * HW_];
__device__ float g_cmax1[B_ * HW_];
__device__ float g_cmin1[B_ * HW_];
__device__ float g_s0[B_ * HW_];
__device__ float g_s1[B_ * HW_];
// pre-split, pre-swizzled weight image (exact smem layout, both splits)
__device__ __align__(16) uint16_t g_wbf[73728];   // 147456 B

// ------------------------------------------------------------------
// Kernel 1: per-pixel channel max/min by parity
// ------------------------------------------------------------------
__global__ void chan_reduce_kernel(const float* __restrict__ x) {
    int t = blockIdx.x * blockDim.x + threadIdx.x;
    int b  = t >> 12;
    int hw = t & (HW_ - 1);
    const float* xb = x + (size_t)b * C_ * HW_ + hw;
    float mx0 = -1e30f, mn0 = 1e30f, mx1 = -1e30f, mn1 = 1e30f;
#pragma unroll 8
    for (int c = 0; c < C_; c += 2) {
        float v0 = xb[(size_t)c * HW_];
        float v1 = xb[(size_t)(c + 1) * HW_];
        mx0 = fmaxf(mx0, v0); mn0 = fminf(mn0, v0);
        mx1 = fmaxf(mx1, v1); mn1 = fminf(mn1, v1);
    }
    g_cmax0[t] = mx0; g_cmin0[t] = mn0;
    g_cmax1[t] = mx1; g_cmin1[t] = mn1;
}

// ------------------------------------------------------------------
// Kernel 2: 3x3 replicate-clamped window range -> s=(max-min)+eps
// ------------------------------------------------------------------
__global__ void window_std_kernel() {
    int t = blockIdx.x * blockDim.x + threadIdx.x;
    int b = t >> 12;
    int h = (t >> 6) & 63;
    int w = t & 63;
    int base = b * HW_;
    float mx0 = -1e30f, mn0 = 1e30f, mx1 = -1e30f, mn1 = 1e30f;
#pragma unroll
    for (int di = -1; di <= 1; di++)
#pragma unroll
        for (int dj = -1; dj <= 1; dj++) {
            int hh = min(max(h + di, 0), 63);
            int ww = min(max(w + dj, 0), 63);
            int idx = base + hh * 64 + ww;
            mx0 = fmaxf(mx0, g_cmax0[idx]); mn0 = fminf(mn0, g_cmin0[idx]);
            mx1 = fmaxf(mx1, g_cmax1[idx]); mn1 = fminf(mn1, g_cmin1[idx]);
        }
    g_s0[t] = (mx0 - mn0) + EPSF;
    g_s1[t] = (mx1 - mn1) + EPSF;
}

// ------------------------------------------------------------------
// Kernel 3: weight prep — split fp32 W into (hi,lo) bf16 in the exact smem
// image: [split][par][tap][k2][o 64][16 ch], 16B-half XOR swizzle on o>>2.
// ------------------------------------------------------------------
__global__ void wprep_kernel(const float* __restrict__ Wt) {
    int e = blockIdx.x * blockDim.x + threadIdx.x;   // 0 .. 73727
    if (e >= 73728) return;
    int split  = e / 36864;
    int r      = e % 36864;
    int tile   = r / 1024;
    int within = r % 1024;
    int o  = within / 16;
    int ch = within % 16;
    int k2  = tile & 1;
    int tap = (tile >> 1) % 9;
    int par = tile / 18;
    int i = tap / 3, j = tap % 3;
    int cg = 2 * (k2 * 16 + ch) + par;            // global channel
    float v = Wt[(size_t)o * 576 + cg * 9 + j * 3 + i];
    float hi = __bfloat162float(__float2bfloat16(v));
    uint16_t val;
    if (split == 0) val = __bfloat16_as_ushort(__float2bfloat16(v));
    else            val = __bfloat16_as_ushort(__float2bfloat16(v - hi));
    int kh = ch >> 3, chlo = ch & 7;
    int boff = split * 73728 + tile * 2048
             + o * 32 + ((kh ^ ((o >> 2) & 1)) << 4) + chlo * 2;
    g_wbf[boff >> 1] = val;
}

// ------------------------------------------------------------------
// PTX helpers
// ------------------------------------------------------------------
__device__ __forceinline__ uint32_t smem_to_u32(const void* p) {
    uint32_t a;
    asm("{ .reg .u64 t; cvta.to.shared.u64 t, %1; cvt.u32.u64 %0, t; }"
        : "=r"(a) : "l"(p));
    return a;
}
__device__ __forceinline__ void ldsm4(uint32_t* r, uint32_t addr) {
    asm volatile("ldmatrix.sync.aligned.m8n8.x4.shared.b16 {%0,%1,%2,%3}, [%4];"
                 : "=r"(r[0]), "=r"(r[1]), "=r"(r[2]), "=r"(r[3]) : "r"(addr));
}
__device__ __forceinline__ void mma16816(float* d, const uint32_t* a,
                                         uint32_t b0, uint32_t b1) {
    asm volatile("mma.sync.aligned.m16n8k16.row.col.f32.bf16.bf16.f32 "
                 "{%0,%1,%2,%3}, {%4,%5,%6,%7}, {%8,%9}, {%0,%1,%2,%3};"
                 : "+f"(d[0]), "+f"(d[1]), "+f"(d[2]), "+f"(d[3])
                 : "r"(a[0]), "r"(a[1]), "r"(a[2]), "r"(a[3]), "r"(b0), "r"(b1));
}

// smem layout
#define XS_LO  23040          // X-lo split base (hi at 0); 10*18*128 B each
#define WSOFF  46080          // weight image: 2 * 73728 B
#define SMEM_TOTAL 193536

// ------------------------------------------------------------------
// Main kernel: CTA = batch b, 8 output rows x 16 cols. M=64 (o), N=128 (pix).
// warp wid owns output row s=wid (n = wid*16 + w).
// ------------------------------------------------------------------
__global__ void __launch_bounds__(256, 1)
conv_mma_kernel(const float* __restrict__ x,
                const float* __restrict__ bias,
                float* __restrict__ out) {
    extern __shared__ __align__(16) unsigned char smem[];
    const uint32_t sb32 = smem_to_u32(smem);

    const int tid = threadIdx.x;
    const int wid = tid >> 5;
    const int lid = tid & 31;
    const int b  = blockIdx.z;
    const int h0 = blockIdx.y * 8;
    const int w0 = blockIdx.x * 16;

    // ---- copy pre-split weights (147456 B, L2-resident broadcast) ----
    {
        const uint4* src = reinterpret_cast<const uint4*>(g_wbf);
        uint4* dst = reinterpret_cast<uint4*>(smem + WSOFF);
        for (int i = tid; i < 9216; i += 256) dst[i] = src[i];
    }

    // ---- fill X: 10x18 positions, 64 ch each, split hi/lo, swizzled ----
    const float* xb = x + (size_t)b * C_ * HW_;
    for (int idx = tid; idx < 11520; idx += 256) {
        int ch64 = idx / 180;
        int p    = idx % 180;
        int r    = p / 18;
        int c    = p % 18;
        int hin = min(max(h0 + r - 1, 0), 63);
        int win = min(max(w0 + c - 1, 0), 63);
        float v = xb[(size_t)ch64 * HW_ + hin * 64 + win];
        int par = ch64 & 1, kk = ch64 >> 1;
        int k2 = kk >> 4, ch16 = kk & 15;
        int kh = ch16 >> 3, chlo = ch16 & 7;
        int inner = par * 64 + k2 * 32 + kh * 16;
        int off = r * 2304 + c * 128 + (inner ^ ((c & 7) << 4)) + chlo * 2;
        float hi = __bfloat162float(__float2bfloat16(v));
        *(uint16_t*)(smem + off) = __bfloat16_as_ushort(__float2bfloat16(v));
        *(uint16_t*)(smem + XS_LO + off) = __bfloat16_as_ushort(__float2bfloat16(v - hi));
    }
    __syncthreads();

    // ---- mainloop ----
    const int lm = lid & 15, kh = lid >> 4;
    const uint32_t a_inner = (uint32_t)(lm * 32 + ((kh ^ ((lm >> 2) & 1)) << 4));

    float accE[32], accO[32];
#pragma unroll
    for (int i = 0; i < 32; i++) { accE[i] = 0.f; accO[i] = 0.f; }

    auto gemm_par = [&](float (&acc)[32], int par, uint32_t wbase, uint32_t xbase) {
#pragma unroll 1
        for (int tap = 0; tap < 9; tap++) {
            const int i = tap / 3, j = tap % 3;
            const int cB = lm + j;
            const uint32_t xrow = xbase + (wid + i) * 2304 + cB * 128;
            const uint32_t at0 = wbase + (uint32_t)(((par * 9 + tap) * 2) * 2048) + a_inner;
#pragma unroll
            for (int k2 = 0; k2 < 2; k2++) {
                uint32_t bin = (uint32_t)((par * 64 + k2 * 32 + kh * 16) ^ ((cB & 7) << 4));
                uint32_t bb[4], a0[4], a1[4], a2[4], a3[4];
                ldsm4(bb, xrow + bin);
                uint32_t at = at0 + (uint32_t)(k2 * 2048);
                ldsm4(a0, at);
                ldsm4(a1, at + 512);
                ldsm4(a2, at + 1024);
                ldsm4(a3, at + 1536);
                mma16816(acc + 0,  a0, bb[0], bb[2]);
                mma16816(acc + 4,  a0, bb[1], bb[3]);
                mma16816(acc + 8,  a1, bb[0], bb[2]);
                mma16816(acc + 12, a1, bb[1], bb[3]);
                mma16816(acc + 16, a2, bb[0], bb[2]);
                mma16816(acc + 20, a2, bb[1], bb[3]);
                mma16816(acc + 24, a3, bb[0], bb[2]);
                mma16816(acc + 28, a3, bb[1], bb[3]);
            }
        }
    };

#pragma unroll 1
    for (int term = 0; term < 3; term++) {
        const uint32_t wbase = sb32 + WSOFF + ((term == 2) ? 73728u : 0u);
        const uint32_t xbase = sb32 + ((term == 1) ? (uint32_t)XS_LO : 0u);
        gemm_par(accE, 0, wbase, xbase);
        gemm_par(accO, 1, wbase, xbase);
    }

    // ---- epilogue ----
    const int g = lid >> 2, t4 = lid & 3;
    const int hrow = h0 + wid;
    float i0[2][2], i1[2][2], sc0[2][2], sc1[2][2];
#pragma unroll
    for (int nt = 0; nt < 2; nt++) {
        int wloc = nt * 8 + 2 * t4;
        int sidx = b * HW_ + hrow * 64 + (w0 + wloc);
#pragma unroll
        for (int e = 0; e < 2; e++) {
            float a0v = g_s0[sidx + e], a1v = g_s1[sidx + e];
            sc0[nt][e] = a0v; sc1[nt][e] = a1v;
            i0[nt][e] = 1.0f / a0v; i1[nt][e] = 1.0f / a1v;
        }
    }
#pragma unroll
    for (int mt = 0; mt < 4; mt++) {
#pragma unroll
        for (int half = 0; half < 2; half++) {
            int o = mt * 16 + g + half * 8;
            float bo = bias[o];
            bool odd = (o & 1) != 0;
#pragma unroll
            for (int nt = 0; nt < 2; nt++) {
                float2 vv;
                float* pv = &vv.x;
#pragma unroll
                for (int e = 0; e < 2; e++) {
                    int k = (mt * 2 + nt) * 4 + half * 2 + e;
                    float v = accE[k] * i0[nt][e] + accO[k] * i1[nt][e] + bo;
                    v = (v >= 0.f) ? v : (SLOPE * v);
                    v *= odd ? sc1[nt][e] : sc0[nt][e];
                    pv[e] = v;
                }
                int wloc = nt * 8 + 2 * t4;
                *reinterpret_cast<float2*>(
                    out + ((size_t)(b * O_ + o) * HW_) + hrow * 64 + w0 + wloc) = vv;
            }
        }
    }
}

// ------------------------------------------------------------------
extern "C" void kernel_launch(void* const* d_in, const int* in_sizes, int n_in,
                              void* d_out, int out_size) {
    const float* x    = (const float*)d_in[0];
    const float* Wt   = (const float*)d_in[1];
    const float* bias = (const float*)d_in[2];
    float* out = (float*)d_out;

    cudaFuncSetAttribute(conv_mma_kernel,
                         cudaFuncAttributeMaxDynamicSharedMemorySize, SMEM_TOTAL);

    chan_reduce_kernel<<<(B_ * HW_) / 256, 256>>>(x);
    window_std_kernel<<<(B_ * HW_) / 256, 256>>>();
    wprep_kernel<<<288, 256>>>(Wt);

    dim3 grid(4, 8, 16);   // wtiles, htiles, batch
    conv_mma_kernel<<<grid, 256, SMEM_TOTAL>>>(x, bias, out);
}

// round 6
// speedup vs baseline: 2.6942x; 1.2987x over previous
#include <cuda_runtime.h>
#include <cuda_bf16.h>
#include <cstdint>

#define B_  16
#define C_  64
#define O_  64
#define H_  64
#define Wd_ 64
#define HW_ (H_ * Wd_)
#define EPSF 1e-6f
#define SLOPE 0.01f

// ---- scratch ----
__device__ float g_cmax0[B_ * HW_];
__device__ float g_cmin0[B_ * HW_];
__device__ float g_cmax1[B_ * HW_];
__device__ float g_cmin1[B_ * HW_];
__device__ float g_s0[B_ * HW_];
__device__ float g_s1[B_ * HW_];
// per-lane A-fragment image: [split][par][tap][k2][mt][lane][4 u32] = 36864 u32
__device__ __align__(16) uint32_t g_wfrag[36864];

// ------------------------------------------------------------------
// Kernel 1: per-pixel channel max/min by parity
// ------------------------------------------------------------------
__global__ void chan_reduce_kernel(const float* __restrict__ x) {
    int t = blockIdx.x * blockDim.x + threadIdx.x;
    int b  = t >> 12;
    int hw = t & (HW_ - 1);
    const float* xb = x + (size_t)b * C_ * HW_ + hw;
    float mx0 = -1e30f, mn0 = 1e30f, mx1 = -1e30f, mn1 = 1e30f;
#pragma unroll 8
    for (int c = 0; c < C_; c += 2) {
        float v0 = xb[(size_t)c * HW_];
        float v1 = xb[(size_t)(c + 1) * HW_];
        mx0 = fmaxf(mx0, v0); mn0 = fminf(mn0, v0);
        mx1 = fmaxf(mx1, v1); mn1 = fminf(mn1, v1);
    }
    g_cmax0[t] = mx0; g_cmin0[t] = mn0;
    g_cmax1[t] = mx1; g_cmin1[t] = mn1;
}

// ------------------------------------------------------------------
// Kernel 2: 3x3 replicate-clamped window range -> s=(max-min)+eps
// ------------------------------------------------------------------
__global__ void window_std_kernel() {
    int t = blockIdx.x * blockDim.x + threadIdx.x;
    int b = t >> 12;
    int h = (t >> 6) & 63;
    int w = t & 63;
    int base = b * HW_;
    float mx0 = -1e30f, mn0 = 1e30f, mx1 = -1e30f, mn1 = 1e30f;
#pragma unroll
    for (int di = -1; di <= 1; di++)
#pragma unroll
        for (int dj = -1; dj <= 1; dj++) {
            int hh = min(max(h + di, 0), 63);
            int ww = min(max(w + dj, 0), 63);
            int idx = base + hh * 64 + ww;
            mx0 = fmaxf(mx0, g_cmax0[idx]); mn0 = fminf(mn0, g_cmin0[idx]);
            mx1 = fmaxf(mx1, g_cmax1[idx]); mn1 = fminf(mn1, g_cmin1[idx]);
        }
    g_s0[t] = (mx0 - mn0) + EPSF;
    g_s1[t] = (mx1 - mn1) + EPSF;
}

// ------------------------------------------------------------------
// Kernel 3: weight prep -> per-lane mma A fragments (PTX m16n8k16 layout).
// a0=(r,c) a1=(r+8,c) a2=(r,c+8) a3=(r+8,c+8); r=lane>>2, c=(lane&3)*2.
// u32 e -> q(a-reg), lane, mt, k2, tap, par, split.
// ------------------------------------------------------------------
__global__ void wprep_kernel(const float* __restrict__ Wt) {
    int e = blockIdx.x * blockDim.x + threadIdx.x;
    if (e >= 36864) return;
    int q    = e & 3;
    int lane = (e >> 2) & 31;
    int mt   = (e >> 7) & 3;
    int rest = e >> 9;
    int k2   = rest & 1;  rest >>= 1;
    int tap  = rest % 9;  rest /= 9;
    int par  = rest & 1;
    int split = rest >> 1;

    int r = lane >> 2, c = (lane & 3) * 2;
    int o  = mt * 16 + r + ((q & 1) ? 8 : 0);
    int ch = c + ((q & 2) ? 8 : 0);
    int i = tap / 3, j = tap % 3;

    uint32_t packed = 0;
#pragma unroll
    for (int hp = 0; hp < 2; hp++) {
        int cg = 2 * (k2 * 16 + ch + hp) + par;      // global channel
        float v = Wt[(size_t)o * 576 + cg * 9 + j * 3 + i];
        uint16_t val;
        if (split == 0) {
            val = __bfloat16_as_ushort(__float2bfloat16(v));
        } else {
            float hi = __bfloat162float(__float2bfloat16(v));
            val = __bfloat16_as_ushort(__float2bfloat16(v - hi));
        }
        packed |= (uint32_t)val << (hp * 16);
    }
    g_wfrag[e] = packed;
}

// ------------------------------------------------------------------
// PTX helpers
// ------------------------------------------------------------------
__device__ __forceinline__ uint32_t smem_to_u32(const void* p) {
    uint32_t a;
    asm("{ .reg .u64 t; cvta.to.shared.u64 t, %1; cvt.u32.u64 %0, t; }"
        : "=r"(a) : "l"(p));
    return a;
}
__device__ __forceinline__ void ldsm4(uint32_t* r, uint32_t addr) {
    asm volatile("ldmatrix.sync.aligned.m8n8.x4.shared.b16 {%0,%1,%2,%3}, [%4];"
                 : "=r"(r[0]), "=r"(r[1]), "=r"(r[2]), "=r"(r[3]) : "r"(addr));
}
__device__ __forceinline__ void mma16816(float* d, const uint4 a,
                                         uint32_t b0, uint32_t b1) {
    asm volatile("mma.sync.aligned.m16n8k16.row.col.f32.bf16.bf16.f32 "
                 "{%0,%1,%2,%3}, {%4,%5,%6,%7}, {%8,%9}, {%0,%1,%2,%3};"
                 : "+f"(d[0]), "+f"(d[1]), "+f"(d[2]), "+f"(d[3])
                 : "r"(a.x), "r"(a.y), "r"(a.z), "r"(a.w), "r"(b0), "r"(b1));
}

// smem: X hi split at 0, lo split at XS_LO; 10 rows * 18 cols * 128B each
#define XS_LO  23040
#define SMEM_TOTAL 46080

// ------------------------------------------------------------------
// Main kernel: CTA = batch b, 8 output rows x 16 cols. M=64 (o), N=128 (pix).
// Warp wid owns output row s=wid. Weights come from g_wfrag via LDG (L1-hot).
// ------------------------------------------------------------------
__global__ void __launch_bounds__(256, 2)
conv_mma_kernel(const float* __restrict__ x,
                const float* __restrict__ bias,
                float* __restrict__ out) {
    extern __shared__ __align__(16) unsigned char smem[];
    const uint32_t sb32 = smem_to_u32(smem);

    const int tid = threadIdx.x;
    const int wid = tid >> 5;
    const int lid = tid & 31;
    const int b  = blockIdx.z;
    const int h0 = blockIdx.y * 8;
    const int w0 = blockIdx.x * 16;

    // ---- fill X: 10x18 positions, 64 ch each, split hi/lo, swizzled ----
    const float* xb = x + (size_t)b * C_ * HW_;
    for (int idx = tid; idx < 11520; idx += 256) {
        int ch64 = idx / 180;
        int p    = idx % 180;
        int r    = p / 18;
        int c    = p % 18;
        int hin = min(max(h0 + r - 1, 0), 63);
        int win = min(max(w0 + c - 1, 0), 63);
        float v = xb[(size_t)ch64 * HW_ + hin * 64 + win];
        int par = ch64 & 1, kk = ch64 >> 1;
        int k2 = kk >> 4, ch16 = kk & 15;
        int kh = ch16 >> 3, chlo = ch16 & 7;
        int inner = par * 64 + k2 * 32 + kh * 16;
        int off = r * 2304 + c * 128 + (inner ^ ((c & 7) << 4)) + chlo * 2;
        float hi = __bfloat162float(__float2bfloat16(v));
        *(uint16_t*)(smem + off) = __bfloat16_as_ushort(__float2bfloat16(v));
        *(uint16_t*)(smem + XS_LO + off) = __bfloat16_as_ushort(__float2bfloat16(v - hi));
    }
    __syncthreads();

    // ---- mainloop ----
    const int lm = lid & 15, kh = lid >> 4;

    float accE[32], accO[32];
#pragma unroll
    for (int i = 0; i < 32; i++) { accE[i] = 0.f; accO[i] = 0.f; }

    const uint4* __restrict__ wf = reinterpret_cast<const uint4*>(g_wfrag);

    auto gemm_par = [&](float (&acc)[32], int split, int par, uint32_t xbase) {
        // uint4 base for (split,par): blocks of 9 taps * 2 k2 * 4 mt * 32 lanes
        const uint4* wsp = wf + (size_t)((split * 2 + par) * 9) * (2 * 4 * 32) + lid;
#pragma unroll 1
        for (int tap = 0; tap < 9; tap++) {
            const int i = tap / 3, j = tap % 3;
            const int cB = lm + j;
            const uint32_t xrow = xbase + (wid + i) * 2304 + cB * 128;
            const uint32_t binbase = (uint32_t)((par * 64 + kh * 16) ^ ((cB & 7) << 4));
            const uint4* wtap = wsp + tap * (2 * 4 * 32);
#pragma unroll
            for (int k2 = 0; k2 < 2; k2++) {
                uint32_t bb[4];
                ldsm4(bb, xrow + (binbase ^ (uint32_t)(k2 * 32)));
                const uint4* wk = wtap + k2 * (4 * 32);
                uint4 a0 = wk[0];
                uint4 a1 = wk[32];
                uint4 a2 = wk[64];
                uint4 a3 = wk[96];
                mma16816(acc + 0,  a0, bb[0], bb[2]);
                mma16816(acc + 4,  a0, bb[1], bb[3]);
                mma16816(acc + 8,  a1, bb[0], bb[2]);
                mma16816(acc + 12, a1, bb[1], bb[3]);
                mma16816(acc + 16, a2, bb[0], bb[2]);
                mma16816(acc + 20, a2, bb[1], bb[3]);
                mma16816(acc + 24, a3, bb[0], bb[2]);
                mma16816(acc + 28, a3, bb[1], bb[3]);
            }
        }
    };

    // term0: Whi*Xhi, term1: Whi*Xlo, term2: Wlo*Xhi
#pragma unroll 1
    for (int term = 0; term < 3; term++) {
        const int split = (term == 2) ? 1 : 0;
        const uint32_t xbase = sb32 + ((term == 1) ? (uint32_t)XS_LO : 0u);
        gemm_par(accE, split, 0, xbase);
        gemm_par(accO, split, 1, xbase);
    }

    // ---- epilogue ----
    const int g = lid >> 2, t4 = lid & 3;
    const int hrow = h0 + wid;
    float i0[2][2], i1[2][2], sc0[2][2], sc1[2][2];
#pragma unroll
    for (int nt = 0; nt < 2; nt++) {
        int wloc = nt * 8 + 2 * t4;
        int sidx = b * HW_ + hrow * 64 + (w0 + wloc);
#pragma unroll
        for (int e = 0; e < 2; e++) {
            float a0v = g_s0[sidx + e], a1v = g_s1[sidx + e];
            sc0[nt][e] = a0v; sc1[nt][e] = a1v;
            i0[nt][e] = 1.0f / a0v; i1[nt][e] = 1.0f / a1v;
        }
    }
#pragma unroll
    for (int mt = 0; mt < 4; mt++) {
#pragma unroll
        for (int half = 0; half < 2; half++) {
            int o = mt * 16 + g + half * 8;
            float bo = bias[o];
            bool odd = (o & 1) != 0;
#pragma unroll
            for (int nt = 0; nt < 2; nt++) {
                float2 vv;
                float* pv = &vv.x;
#pragma unroll
                for (int e = 0; e < 2; e++) {
                    int k = (mt * 2 + nt) * 4 + half * 2 + e;
                    float v = accE[k] * i0[nt][e] + accO[k] * i1[nt][e] + bo;
                    v = (v >= 0.f) ? v : (SLOPE * v);
                    v *= odd ? sc1[nt][e] : sc0[nt][e];
                    pv[e] = v;
                }
                int wloc = nt * 8 + 2 * t4;
                *reinterpret_cast<float2*>(
                    out + ((size_t)(b * O_ + o) * HW_) + hrow * 64 + w0 + wloc) = vv;
            }
        }
    }
}

// ------------------------------------------------------------------
extern "C" void kernel_launch(void* const* d_in, const int* in_sizes, int n_in,
                              void* d_out, int out_size) {
    const float* x    = (const float*)d_in[0];
    const float* Wt   = (const float*)d_in[1];
    const float* bias = (const float*)d_in[2];
    float* out = (float*)d_out;

    cudaFuncSetAttribute(conv_mma_kernel,
                         cudaFuncAttributeMaxDynamicSharedMemorySize, SMEM_TOTAL);

    chan_reduce_kernel<<<(B_ * HW_) / 256, 256>>>(x);
    window_std_kernel<<<(B_ * HW_) / 256, 256>>>();
    wprep_kernel<<<144, 256>>>(Wt);

    dim3 grid(4, 8, 16);   // wtiles, htiles, batch
    conv_mma_kernel<<<grid, 256, SMEM_TOTAL>>>(x, bias, out);
}

// round 7
// speedup vs baseline: 2.7101x; 1.0059x over previous
#include <cuda_runtime.h>
#include <cuda_bf16.h>
#include <cstdint>

#define B_  16
#define C_  64
#define O_  64
#define H_  64
#define Wd_ 64
#define HW_ (H_ * Wd_)
#define EPSF 1e-6f
#define SLOPE 0.01f

// ---- scratch ----
__device__ float g_cmax0[B_ * HW_];
__device__ float g_cmin0[B_ * HW_];
__device__ float g_cmax1[B_ * HW_];
__device__ float g_cmin1[B_ * HW_];
__device__ float g_s0[B_ * HW_];
__device__ float g_s1[B_ * HW_];
// per-lane A-fragment image: [split][par][tap][k2][mt][lane][4 u32] = 36864 u32
__device__ __align__(16) uint32_t g_wfrag[36864];

// ------------------------------------------------------------------
// Kernel 1: per-pixel channel max/min by parity (float4 over w, 4 px/thread)
// ------------------------------------------------------------------
__global__ void chan_reduce_kernel(const float* __restrict__ x) {
    int t = blockIdx.x * blockDim.x + threadIdx.x;      // 0 .. 16383
    int b   = t >> 10;
    int hw4 = t & 1023;                                 // group of 4 pixels
    const float4* xb = reinterpret_cast<const float4*>(x + (size_t)b * C_ * HW_) + hw4;

    float4 mx0 = make_float4(-1e30f, -1e30f, -1e30f, -1e30f);
    float4 mn0 = make_float4( 1e30f,  1e30f,  1e30f,  1e30f);
    float4 mx1 = mx0, mn1 = mn0;
#pragma unroll 4
    for (int c = 0; c < C_; c += 2) {
        float4 v0 = xb[(size_t)c * (HW_ / 4)];
        float4 v1 = xb[(size_t)(c + 1) * (HW_ / 4)];
        mx0.x = fmaxf(mx0.x, v0.x); mn0.x = fminf(mn0.x, v0.x);
        mx0.y = fmaxf(mx0.y, v0.y); mn0.y = fminf(mn0.y, v0.y);
        mx0.z = fmaxf(mx0.z, v0.z); mn0.z = fminf(mn0.z, v0.z);
        mx0.w = fmaxf(mx0.w, v0.w); mn0.w = fminf(mn0.w, v0.w);
        mx1.x = fmaxf(mx1.x, v1.x); mn1.x = fminf(mn1.x, v1.x);
        mx1.y = fmaxf(mx1.y, v1.y); mn1.y = fminf(mn1.y, v1.y);
        mx1.z = fmaxf(mx1.z, v1.z); mn1.z = fminf(mn1.z, v1.z);
        mx1.w = fmaxf(mx1.w, v1.w); mn1.w = fminf(mn1.w, v1.w);
    }
    int base = b * HW_ + hw4 * 4;
    reinterpret_cast<float4*>(g_cmax0 + base)[0] = mx0;
    reinterpret_cast<float4*>(g_cmin0 + base)[0] = mn0;
    reinterpret_cast<float4*>(g_cmax1 + base)[0] = mx1;
    reinterpret_cast<float4*>(g_cmin1 + base)[0] = mn1;
}

// ------------------------------------------------------------------
// Kernel 2: 3x3 replicate-clamped window range -> s=(max-min)+eps
// ------------------------------------------------------------------
__global__ void window_std_kernel() {
    int t = blockIdx.x * blockDim.x + threadIdx.x;
    int b = t >> 12;
    int h = (t >> 6) & 63;
    int w = t & 63;
    int base = b * HW_;
    float mx0 = -1e30f, mn0 = 1e30f, mx1 = -1e30f, mn1 = 1e30f;
#pragma unroll
    for (int di = -1; di <= 1; di++)
#pragma unroll
        for (int dj = -1; dj <= 1; dj++) {
            int hh = min(max(h + di, 0), 63);
            int ww = min(max(w + dj, 0), 63);
            int idx = base + hh * 64 + ww;
            mx0 = fmaxf(mx0, g_cmax0[idx]); mn0 = fminf(mn0, g_cmin0[idx]);
            mx1 = fmaxf(mx1, g_cmax1[idx]); mn1 = fminf(mn1, g_cmin1[idx]);
        }
    g_s0[t] = (mx0 - mn0) + EPSF;
    g_s1[t] = (mx1 - mn1) + EPSF;
}

// ------------------------------------------------------------------
// Kernel 3: weight prep -> per-lane mma A fragments (PTX m16n8k16 layout).
// ------------------------------------------------------------------
__global__ void wprep_kernel(const float* __restrict__ Wt) {
    int e = blockIdx.x * blockDim.x + threadIdx.x;
    if (e >= 36864) return;
    int q    = e & 3;
    int lane = (e >> 2) & 31;
    int mt   = (e >> 7) & 3;
    int rest = e >> 9;
    int k2   = rest & 1;  rest >>= 1;
    int tap  = rest % 9;  rest /= 9;
    int par  = rest & 1;
    int split = rest >> 1;

    int r = lane >> 2, c = (lane & 3) * 2;
    int o  = mt * 16 + r + ((q & 1) ? 8 : 0);
    int ch = c + ((q & 2) ? 8 : 0);
    int i = tap / 3, j = tap % 3;

    uint32_t packed = 0;
#pragma unroll
    for (int hp = 0; hp < 2; hp++) {
        int cg = 2 * (k2 * 16 + ch + hp) + par;      // global channel
        float v = Wt[(size_t)o * 576 + cg * 9 + j * 3 + i];
        uint16_t val;
        if (split == 0) {
            val = __bfloat16_as_ushort(__float2bfloat16(v));
        } else {
            float hi = __bfloat162float(__float2bfloat16(v));
            val = __bfloat16_as_ushort(__float2bfloat16(v - hi));
        }
        packed |= (uint32_t)val << (hp * 16);
    }
    g_wfrag[e] = packed;
}

// ------------------------------------------------------------------
// PTX helpers
// ------------------------------------------------------------------
__device__ __forceinline__ uint32_t smem_to_u32(const void* p) {
    uint32_t a;
    asm("{ .reg .u64 t; cvta.to.shared.u64 t, %1; cvt.u32.u64 %0, t; }"
        : "=r"(a) : "l"(p));
    return a;
}
__device__ __forceinline__ void ldsm4(uint32_t* r, uint32_t addr) {
    asm volatile("ldmatrix.sync.aligned.m8n8.x4.shared.b16 {%0,%1,%2,%3}, [%4];"
                 : "=r"(r[0]), "=r"(r[1]), "=r"(r[2]), "=r"(r[3]) : "r"(addr));
}
__device__ __forceinline__ void mma16816(float* d, const uint4 a,
                                         uint32_t b0, uint32_t b1) {
    asm volatile("mma.sync.aligned.m16n8k16.row.col.f32.bf16.bf16.f32 "
                 "{%0,%1,%2,%3}, {%4,%5,%6,%7}, {%8,%9}, {%0,%1,%2,%3};"
                 : "+f"(d[0]), "+f"(d[1]), "+f"(d[2]), "+f"(d[3])
                 : "r"(a.x), "r"(a.y), "r"(a.z), "r"(a.w), "r"(b0), "r"(b1));
}

// smem: X hi split at 0, lo split at XS_LO; 10 rows * 18 cols * 128B each
#define XS_LO  23040
#define SMEM_TOTAL 46080

// ------------------------------------------------------------------
// Main kernel: CTA = batch b, 8 output rows x 16 cols. M=64 (o), N=128 (pix).
// Warp wid owns output row s=wid. Weights from g_wfrag via LDG (L1-hot).
// ------------------------------------------------------------------
__global__ void __launch_bounds__(256, 2)
conv_mma_kernel(const float* __restrict__ x,
                const float* __restrict__ bias,
                float* __restrict__ out) {
    extern __shared__ __align__(16) unsigned char smem[];
    const uint32_t sb32 = smem_to_u32(smem);

    const int tid = threadIdx.x;
    const int wid = tid >> 5;
    const int lid = tid & 31;
    const int b  = blockIdx.z;
    const int h0 = blockIdx.y * 8;
    const int w0 = blockIdx.x * 16;

    // ---- fill X: 10x18 positions, 64 ch each, split hi/lo, swizzled ----
    const float* xb = x + (size_t)b * C_ * HW_;
    for (int idx = tid; idx < 11520; idx += 256) {
        int ch64 = idx / 180;
        int p    = idx % 180;
        int r    = p / 18;
        int c    = p % 18;
        int hin = min(max(h0 + r - 1, 0), 63);
        int win = min(max(w0 + c - 1, 0), 63);
        float v = xb[(size_t)ch64 * HW_ + hin * 64 + win];
        int par = ch64 & 1, kk = ch64 >> 1;
        int k2 = kk >> 4, ch16 = kk & 15;
        int kh = ch16 >> 3, chlo = ch16 & 7;
        int inner = par * 64 + k2 * 32 + kh * 16;
        int off = r * 2304 + c * 128 + (inner ^ ((c & 7) << 4)) + chlo * 2;
        float hi = __bfloat162float(__float2bfloat16(v));
        *(uint16_t*)(smem + off) = __bfloat16_as_ushort(__float2bfloat16(v));
        *(uint16_t*)(smem + XS_LO + off) = __bfloat16_as_ushort(__float2bfloat16(v - hi));
    }
    __syncthreads();

    // ---- mainloop ----
    const int lm = lid & 15, kh = lid >> 4;

    // hoisted per-lane address pieces
    uint32_t rowb[3];      // xrow base per i (minus split base)
    uint32_t colj[3];      // cB*128 per j
    uint32_t swzj[3];      // ((cB&7)<<4) per j
#pragma unroll
    for (int i = 0; i < 3; i++) rowb[i] = (uint32_t)((wid + i) * 2304);
#pragma unroll
    for (int j = 0; j < 3; j++) {
        int cB = lm + j;
        colj[j] = (uint32_t)(cB * 128);
        swzj[j] = (uint32_t)((cB & 7) << 4);
    }
    const uint32_t kh16 = (uint32_t)(kh * 16);

    float accE[32], accO[32];
#pragma unroll
    for (int i = 0; i < 32; i++) { accE[i] = 0.f; accO[i] = 0.f; }

    const uint4* __restrict__ wf = reinterpret_cast<const uint4*>(g_wfrag);

    auto gemm_par = [&](float (&acc)[32], int split, int par, uint32_t xbase) {
        const uint4* wsp = wf + (size_t)((split * 2 + par) * 9) * 256 + lid;
        const uint32_t parq = (uint32_t)(par * 64) + kh16;
#pragma unroll
        for (int tap = 0; tap < 9; tap++) {
            const int i = tap / 3, j = tap % 3;
            const uint32_t xrow = xbase + rowb[i] + colj[j];
            const uint32_t bin0 = parq ^ swzj[j];
            const uint4* wtap = wsp + tap * 256;
#pragma unroll
            for (int k2 = 0; k2 < 2; k2++) {
                uint32_t bb[4];
                ldsm4(bb, xrow + (bin0 ^ (uint32_t)(k2 << 5)));
                const uint4* wk = wtap + k2 * 128;
                uint4 a0 = wk[0];
                uint4 a1 = wk[32];
                uint4 a2 = wk[64];
                uint4 a3 = wk[96];
                mma16816(acc + 0,  a0, bb[0], bb[2]);
                mma16816(acc + 4,  a0, bb[1], bb[3]);
                mma16816(acc + 8,  a1, bb[0], bb[2]);
                mma16816(acc + 12, a1, bb[1], bb[3]);
                mma16816(acc + 16, a2, bb[0], bb[2]);
                mma16816(acc + 20, a2, bb[1], bb[3]);
                mma16816(acc + 24, a3, bb[0], bb[2]);
                mma16816(acc + 28, a3, bb[1], bb[3]);
            }
        }
    };

    // term0: Whi*Xhi, term1: Whi*Xlo, term2: Wlo*Xhi
#pragma unroll 1
    for (int term = 0; term < 3; term++) {
        const int split = (term == 2) ? 1 : 0;
        const uint32_t xbase = sb32 + ((term == 1) ? (uint32_t)XS_LO : 0u);
        gemm_par(accE, split, 0, xbase);
        gemm_par(accO, split, 1, xbase);
    }

    // ---- epilogue ----
    const int g = lid >> 2, t4 = lid & 3;
    const int hrow = h0 + wid;
    float i0[2][2], i1[2][2], sc0[2][2], sc1[2][2];
#pragma unroll
    for (int nt = 0; nt < 2; nt++) {
        int wloc = nt * 8 + 2 * t4;
        int sidx = b * HW_ + hrow * 64 + (w0 + wloc);
#pragma unroll
        for (int e = 0; e < 2; e++) {
            float a0v = g_s0[sidx + e], a1v = g_s1[sidx + e];
            sc0[nt][e] = a0v; sc1[nt][e] = a1v;
            i0[nt][e] = 1.0f / a0v; i1[nt][e] = 1.0f / a1v;
        }
    }
#pragma unroll
    for (int mt = 0; mt < 4; mt++) {
#pragma unroll
        for (int half = 0; half < 2; half++) {
            int o = mt * 16 + g + half * 8;
            float bo = bias[o];
            bool odd = (o & 1) != 0;
#pragma unroll
            for (int nt = 0; nt < 2; nt++) {
                float2 vv;
                float* pv = &vv.x;
#pragma unroll
                for (int e = 0; e < 2; e++) {
                    int k = (mt * 2 + nt) * 4 + half * 2 + e;
                    float v = accE[k] * i0[nt][e] + accO[k] * i1[nt][e] + bo;
                    v = (v >= 0.f) ? v : (SLOPE * v);
                    v *= odd ? sc1[nt][e] : sc0[nt][e];
                    pv[e] = v;
                }
                int wloc = nt * 8 + 2 * t4;
                *reinterpret_cast<float2*>(
                    out + ((size_t)(b * O_ + o) * HW_) + hrow * 64 + w0 + wloc) = vv;
            }
        }
    }
}

// ------------------------------------------------------------------
extern "C" void kernel_launch(void* const* d_in, const int* in_sizes, int n_in,
                              void* d_out, int out_size) {
    const float* x    = (const float*)d_in[0];
    const float* Wt   = (const float*)d_in[1];
    const float* bias = (const float*)d_in[2];
    float* out = (float*)d_out;

    cudaFuncSetAttribute(conv_mma_kernel,
                         cudaFuncAttributeMaxDynamicSharedMemorySize, SMEM_TOTAL);

    chan_reduce_kernel<<<(B_ * HW_ / 4) / 256, 256>>>(x);
    window_std_kernel<<<(B_ * HW_) / 256, 256>>>();
    wprep_kernel<<<144, 256>>>(Wt);

    dim3 grid(4, 8, 16);   // wtiles, htiles, batch
    conv_mma_kernel<<<grid, 256, SMEM_TOTAL>>>(x, bias, out);
}

// round 8
// speedup vs baseline: 4.3194x; 1.5938x over previous
#include <cuda_runtime.h>
#include <cuda_fp16.h>
#include <cstdint>

#define B_  16
#define C_  64
#define O_  64
#define H_  64
#define Wd_ 64
#define HW_ (H_ * Wd_)
#define EPSF 1e-6f
#define SLOPE 0.01f

// ---- scratch ----
__device__ float g_cmax0[B_ * HW_];
__device__ float g_cmin0[B_ * HW_];
__device__ float g_cmax1[B_ * HW_];
__device__ float g_cmin1[B_ * HW_];
__device__ float g_s0[B_ * HW_];
__device__ float g_s1[B_ * HW_];
// per-lane A-fragment image: [par][tap][k2][mt][lane][4 u32] = 18432 u32 (fp16x2)
__device__ __align__(16) uint32_t g_wfrag[18432];

// ------------------------------------------------------------------
// Kernel 1: per-pixel channel max/min by parity (float4 over w)
// ------------------------------------------------------------------
__global__ void chan_reduce_kernel(const float* __restrict__ x) {
    int t = blockIdx.x * blockDim.x + threadIdx.x;      // 0 .. 16383
    int b   = t >> 10;
    int hw4 = t & 1023;
    const float4* xb = reinterpret_cast<const float4*>(x + (size_t)b * C_ * HW_) + hw4;

    float4 mx0 = make_float4(-1e30f, -1e30f, -1e30f, -1e30f);
    float4 mn0 = make_float4( 1e30f,  1e30f,  1e30f,  1e30f);
    float4 mx1 = mx0, mn1 = mn0;
#pragma unroll 4
    for (int c = 0; c < C_; c += 2) {
        float4 v0 = xb[(size_t)c * (HW_ / 4)];
        float4 v1 = xb[(size_t)(c + 1) * (HW_ / 4)];
        mx0.x = fmaxf(mx0.x, v0.x); mn0.x = fminf(mn0.x, v0.x);
        mx0.y = fmaxf(mx0.y, v0.y); mn0.y = fminf(mn0.y, v0.y);
        mx0.z = fmaxf(mx0.z, v0.z); mn0.z = fminf(mn0.z, v0.z);
        mx0.w = fmaxf(mx0.w, v0.w); mn0.w = fminf(mn0.w, v0.w);
        mx1.x = fmaxf(mx1.x, v1.x); mn1.x = fminf(mn1.x, v1.x);
        mx1.y = fmaxf(mx1.y, v1.y); mn1.y = fminf(mn1.y, v1.y);
        mx1.z = fmaxf(mx1.z, v1.z); mn1.z = fminf(mn1.z, v1.z);
        mx1.w = fmaxf(mx1.w, v1.w); mn1.w = fminf(mn1.w, v1.w);
    }
    int base = b * HW_ + hw4 * 4;
    reinterpret_cast<float4*>(g_cmax0 + base)[0] = mx0;
    reinterpret_cast<float4*>(g_cmin0 + base)[0] = mn0;
    reinterpret_cast<float4*>(g_cmax1 + base)[0] = mx1;
    reinterpret_cast<float4*>(g_cmin1 + base)[0] = mn1;
}

// ------------------------------------------------------------------
// Kernel 2: 3x3 replicate-clamped window range -> s=(max-min)+eps
// ------------------------------------------------------------------
__global__ void window_std_kernel() {
    int t = blockIdx.x * blockDim.x + threadIdx.x;
    int b = t >> 12;
    int h = (t >> 6) & 63;
    int w = t & 63;
    int base = b * HW_;
    float mx0 = -1e30f, mn0 = 1e30f, mx1 = -1e30f, mn1 = 1e30f;
#pragma unroll
    for (int di = -1; di <= 1; di++)
#pragma unroll
        for (int dj = -1; dj <= 1; dj++) {
            int hh = min(max(h + di, 0), 63);
            int ww = min(max(w + dj, 0), 63);
            int idx = base + hh * 64 + ww;
            mx0 = fmaxf(mx0, g_cmax0[idx]); mn0 = fminf(mn0, g_cmin0[idx]);
            mx1 = fmaxf(mx1, g_cmax1[idx]); mn1 = fminf(mn1, g_cmin1[idx]);
        }
    g_s0[t] = (mx0 - mn0) + EPSF;
    g_s1[t] = (mx1 - mn1) + EPSF;
}

// ------------------------------------------------------------------
// Kernel 3: weight prep -> per-lane fp16 mma A fragments (m16n8k16 layout).
// a0=(r,c) a1=(r+8,c) a2=(r,c+8) a3=(r+8,c+8); r=lane>>2, c=(lane&3)*2.
// ------------------------------------------------------------------
__global__ void wprep_kernel(const float* __restrict__ Wt) {
    int e = blockIdx.x * blockDim.x + threadIdx.x;
    if (e >= 18432) return;
    int q    = e & 3;
    int lane = (e >> 2) & 31;
    int mt   = (e >> 7) & 3;
    int rest = e >> 9;
    int k2   = rest & 1;  rest >>= 1;
    int tap  = rest % 9;  rest /= 9;
    int par  = rest & 1;

    int r = lane >> 2, c = (lane & 3) * 2;
    int o  = mt * 16 + r + ((q & 1) ? 8 : 0);
    int ch = c + ((q & 2) ? 8 : 0);
    int i = tap / 3, j = tap % 3;

    uint32_t packed = 0;
#pragma unroll
    for (int hp = 0; hp < 2; hp++) {
        int cg = 2 * (k2 * 16 + ch + hp) + par;      // global channel
        float v = Wt[(size_t)o * 576 + cg * 9 + j * 3 + i];
        packed |= (uint32_t)__half_as_ushort(__float2half(v)) << (hp * 16);
    }
    g_wfrag[e] = packed;
}

// ------------------------------------------------------------------
// PTX helpers
// ------------------------------------------------------------------
__device__ __forceinline__ uint32_t smem_to_u32(const void* p) {
    uint32_t a;
    asm("{ .reg .u64 t; cvta.to.shared.u64 t, %1; cvt.u32.u64 %0, t; }"
        : "=r"(a) : "l"(p));
    return a;
}
__device__ __forceinline__ void ldsm4(uint32_t* r, uint32_t addr) {
    asm volatile("ldmatrix.sync.aligned.m8n8.x4.shared.b16 {%0,%1,%2,%3}, [%4];"
                 : "=r"(r[0]), "=r"(r[1]), "=r"(r[2]), "=r"(r[3]) : "r"(addr));
}
__device__ __forceinline__ void mma16816(float* d, const uint4 a,
                                         uint32_t b0, uint32_t b1) {
    asm volatile("mma.sync.aligned.m16n8k16.row.col.f32.f16.f16.f32 "
                 "{%0,%1,%2,%3}, {%4,%5,%6,%7}, {%8,%9}, {%0,%1,%2,%3};"
                 : "+f"(d[0]), "+f"(d[1]), "+f"(d[2]), "+f"(d[3])
                 : "r"(a.x), "r"(a.y), "r"(a.z), "r"(a.w), "r"(b0), "r"(b1));
}

// smem: X fp16, 10 rows * 18 cols * 128B
#define SMEM_TOTAL 23040

// ------------------------------------------------------------------
// Main kernel: CTA = batch b, 8 output rows x 16 cols. M=64 (o), N=128 (pix).
// Warp wid owns output row s=wid. Weights from g_wfrag via LDG (L1-hot).
// ------------------------------------------------------------------
__global__ void __launch_bounds__(256, 2)
conv_mma_kernel(const float* __restrict__ x,
                const float* __restrict__ bias,
                float* __restrict__ out) {
    extern __shared__ __align__(16) unsigned char smem[];
    const uint32_t sb32 = smem_to_u32(smem);

    const int tid = threadIdx.x;
    const int wid = tid >> 5;
    const int lid = tid & 31;
    const int b  = blockIdx.z;
    const int h0 = blockIdx.y * 8;
    const int w0 = blockIdx.x * 16;

    // ---- fill X: 10x18 positions, 64 ch each, fp16, swizzled ----
    const float* xb = x + (size_t)b * C_ * HW_;
    for (int idx = tid; idx < 11520; idx += 256) {
        int ch64 = idx / 180;
        int p    = idx % 180;
        int r    = p / 18;
        int c    = p % 18;
        int hin = min(max(h0 + r - 1, 0), 63);
        int win = min(max(w0 + c - 1, 0), 63);
        float v = xb[(size_t)ch64 * HW_ + hin * 64 + win];
        int par = ch64 & 1, kk = ch64 >> 1;
        int k2 = kk >> 4, ch16 = kk & 15;
        int kh = ch16 >> 3, chlo = ch16 & 7;
        int inner = par * 64 + k2 * 32 + kh * 16;
        int off = r * 2304 + c * 128 + (inner ^ ((c & 7) << 4)) + chlo * 2;
        *(uint16_t*)(smem + off) = __half_as_ushort(__float2half(v));
    }
    __syncthreads();

    // ---- mainloop ----
    const int lm = lid & 15, kh = lid >> 4;

    uint32_t rowb[3], colj[3], swzj[3];
#pragma unroll
    for (int i = 0; i < 3; i++) rowb[i] = (uint32_t)((wid + i) * 2304);
#pragma unroll
    for (int j = 0; j < 3; j++) {
        int cB = lm + j;
        colj[j] = (uint32_t)(cB * 128);
        swzj[j] = (uint32_t)((cB & 7) << 4);
    }
    const uint32_t kh16 = (uint32_t)(kh * 16);

    float accE[32], accO[32];
#pragma unroll
    for (int i = 0; i < 32; i++) { accE[i] = 0.f; accO[i] = 0.f; }

    const uint4* __restrict__ wf = reinterpret_cast<const uint4*>(g_wfrag);

    auto gemm_par = [&](float (&acc)[32], int par) {
        const uint4* wsp = wf + (size_t)(par * 9) * 256 + lid;
        const uint32_t parq = (uint32_t)(par * 64) + kh16;
#pragma unroll
        for (int tap = 0; tap < 9; tap++) {
            const int i = tap / 3, j = tap % 3;
            const uint32_t xrow = sb32 + rowb[i] + colj[j];
            const uint32_t bin0 = parq ^ swzj[j];
            const uint4* wtap = wsp + tap * 256;
#pragma unroll
            for (int k2 = 0; k2 < 2; k2++) {
                uint32_t bb[4];
                ldsm4(bb, xrow + (bin0 ^ (uint32_t)(k2 << 5)));
                const uint4* wk = wtap + k2 * 128;
                uint4 a0 = wk[0];
                uint4 a1 = wk[32];
                uint4 a2 = wk[64];
                uint4 a3 = wk[96];
                mma16816(acc + 0,  a0, bb[0], bb[2]);
                mma16816(acc + 4,  a0, bb[1], bb[3]);
                mma16816(acc + 8,  a1, bb[0], bb[2]);
                mma16816(acc + 12, a1, bb[1], bb[3]);
                mma16816(acc + 16, a2, bb[0], bb[2]);
                mma16816(acc + 20, a2, bb[1], bb[3]);
                mma16816(acc + 24, a3, bb[0], bb[2]);
                mma16816(acc + 28, a3, bb[1], bb[3]);
            }
        }
    };

    gemm_par(accE, 0);
    gemm_par(accO, 1);

    // ---- epilogue ----
    const int g = lid >> 2, t4 = lid & 3;
    const int hrow = h0 + wid;
    float i0[2][2], i1[2][2], sc0[2][2], sc1[2][2];
#pragma unroll
    for (int nt = 0; nt < 2; nt++) {
        int wloc = nt * 8 + 2 * t4;
        int sidx = b * HW_ + hrow * 64 + (w0 + wloc);
#pragma unroll
        for (int e = 0; e < 2; e++) {
            float a0v = g_s0[sidx + e], a1v = g_s1[sidx + e];
            sc0[nt][e] = a0v; sc1[nt][e] = a1v;
            i0[nt][e] = 1.0f / a0v; i1[nt][e] = 1.0f / a1v;
        }
    }
#pragma unroll
    for (int mt = 0; mt < 4; mt++) {
#pragma unroll
        for (int half = 0; half < 2; half++) {
            int o = mt * 16 + g + half * 8;
            float bo = bias[o];
            bool odd = (o & 1) != 0;
#pragma unroll
            for (int nt = 0; nt < 2; nt++) {
                float2 vv;
                float* pv = &vv.x;
#pragma unroll
                for (int e = 0; e < 2; e++) {
                    int k = (mt * 2 + nt) * 4 + half * 2 + e;
                    float v = accE[k] * i0[nt][e] + accO[k] * i1[nt][e] + bo;
                    v = (v >= 0.f) ? v : (SLOPE * v);
                    v *= odd ? sc1[nt][e] : sc0[nt][e];
                    pv[e] = v;
                }
                int wloc = nt * 8 + 2 * t4;
                *reinterpret_cast<float2*>(
                    out + ((size_t)(b * O_ + o) * HW_) + hrow * 64 + w0 + wloc) = vv;
            }
        }
    }
}

// ------------------------------------------------------------------
extern "C" void kernel_launch(void* const* d_in, const int* in_sizes, int n_in,
                              void* d_out, int out_size) {
    const float* x    = (const float*)d_in[0];
    const float* Wt   = (const float*)d_in[1];
    const float* bias = (const float*)d_in[2];
    float* out = (float*)d_out;

    cudaFuncSetAttribute(conv_mma_kernel,
                         cudaFuncAttributeMaxDynamicSharedMemorySize, SMEM_TOTAL);

    chan_reduce_kernel<<<(B_ * HW_ / 4) / 256, 256>>>(x);
    window_std_kernel<<<(B_ * HW_) / 256, 256>>>();
    wprep_kernel<<<72, 256>>>(Wt);

    dim3 grid(4, 8, 16);   // wtiles, htiles, batch
    conv_mma_kernel<<<grid, 256, SMEM_TOTAL>>>(x, bias, out);
}

// round 9
// speedup vs baseline: 5.1220x; 1.1858x over previous
#include <cuda_runtime.h>
#include <cuda_fp16.h>
#include <cstdint>

#define B_  16
#define C_  64
#define O_  64
#define H_  64
#define Wd_ 64
#define HW_ (H_ * Wd_)
#define EPSF 1e-6f
#define SLOPE 0.01f

// ---- scratch ----
__device__ float g_cmax0[B_ * HW_];
__device__ float g_cmin0[B_ * HW_];
__device__ float g_cmax1[B_ * HW_];
__device__ float g_cmin1[B_ * HW_];
__device__ float g_s0[B_ * HW_];
__device__ float g_s1[B_ * HW_];
// per-lane A-fragment image: [par][tap][k2][mt][lane][4 u32] = 18432 u32 (fp16x2)
__device__ __align__(16) uint32_t g_wfrag[18432];
// NHWC-permuted fp16 x: [b][h][w][cperm] — 128 B per pixel
__device__ __align__(16) unsigned char g_xh[B_ * HW_ * 128];

// cperm(ch) = par*32 + k2*16 + kh*8 + chlo   (matches MMA smem row layout)

// ------------------------------------------------------------------
// Kernel 1 (fused): per-pixel channel min/max by parity + NHWC fp16 pack.
// Block: 64 pixels of one batch. Thread (c4 = tid>>6, px = tid&63) reads
// 16 channels (c4+4k) of its pixel.
// ------------------------------------------------------------------
__global__ void __launch_bounds__(256)
chan_pack_kernel(const float* __restrict__ x) {
    __shared__ unsigned char stage[8192];     // 64 px * 128 B
    __shared__ float s_mx[4][64], s_mn[4][64];

    const int tid = threadIdx.x;
    const int c4 = tid >> 6;
    const int px = tid & 63;
    const int b   = blockIdx.y;
    const int px0 = blockIdx.x * 64;

    const float* xb = x + (size_t)b * C_ * HW_ + px0 + px;
    float mx = -1e30f, mn = 1e30f;
#pragma unroll
    for (int k = 0; k < 16; k++) {
        int ch = c4 + 4 * k;
        float v = xb[(size_t)ch * HW_];
        mx = fmaxf(mx, v); mn = fminf(mn, v);
        // cperm
        int par = ch & 1, kk = ch >> 1;
        int k2 = kk >> 4, ch16 = kk & 15;
        int kh = ch16 >> 3, chlo = ch16 & 7;
        int cperm = par * 32 + k2 * 16 + kh * 8 + chlo;
        int chunk = cperm >> 3;                       // par*4+k2*2+kh
        int soff = px * 128 + ((chunk ^ (px & 7)) << 4) + chlo * 2;
        *(uint16_t*)(stage + soff) = __half_as_ushort(__float2half(v));
    }
    s_mx[c4][px] = mx; s_mn[c4][px] = mn;
    __syncthreads();

    // write minmax (threads 0..63)
    if (tid < 64) {
        int gi = b * HW_ + px0 + tid;
        g_cmax0[gi] = fmaxf(s_mx[0][tid], s_mx[2][tid]);
        g_cmin0[gi] = fminf(s_mn[0][tid], s_mn[2][tid]);
        g_cmax1[gi] = fmaxf(s_mx[1][tid], s_mx[3][tid]);
        g_cmin1[gi] = fminf(s_mn[1][tid], s_mn[3][tid]);
    }

    // write packed rows: 512 chunks of 16B, 2 per thread, coalesced
    unsigned char* dstb = g_xh + ((size_t)(b * HW_ + px0)) * 128;
#pragma unroll
    for (int t = 0; t < 2; t++) {
        int ci = tid * 2 + t;
        int row = ci >> 3, chunk = ci & 7;
        uint4 v = *(const uint4*)(stage + row * 128 + ((chunk ^ (row & 7)) << 4));
        *(uint4*)(dstb + row * 128 + chunk * 16) = v;
    }
}

// ------------------------------------------------------------------
// Kernel 2: 3x3 replicate-clamped window range -> s=(max-min)+eps
// ------------------------------------------------------------------
__global__ void window_std_kernel() {
    int t = blockIdx.x * blockDim.x + threadIdx.x;
    int b = t >> 12;
    int h = (t >> 6) & 63;
    int w = t & 63;
    int base = b * HW_;
    float mx0 = -1e30f, mn0 = 1e30f, mx1 = -1e30f, mn1 = 1e30f;
#pragma unroll
    for (int di = -1; di <= 1; di++)
#pragma unroll
        for (int dj = -1; dj <= 1; dj++) {
            int hh = min(max(h + di, 0), 63);
            int ww = min(max(w + dj, 0), 63);
            int idx = base + hh * 64 + ww;
            mx0 = fmaxf(mx0, g_cmax0[idx]); mn0 = fminf(mn0, g_cmin0[idx]);
            mx1 = fmaxf(mx1, g_cmax1[idx]); mn1 = fminf(mn1, g_cmin1[idx]);
        }
    g_s0[t] = (mx0 - mn0) + EPSF;
    g_s1[t] = (mx1 - mn1) + EPSF;
}

// ------------------------------------------------------------------
// Kernel 3: weight prep -> per-lane fp16 mma A fragments (m16n8k16 layout).
// ------------------------------------------------------------------
__global__ void wprep_kernel(const float* __restrict__ Wt) {
    int e = blockIdx.x * blockDim.x + threadIdx.x;
    if (e >= 18432) return;
    int q    = e & 3;
    int lane = (e >> 2) & 31;
    int mt   = (e >> 7) & 3;
    int rest = e >> 9;
    int k2   = rest & 1;  rest >>= 1;
    int tap  = rest % 9;  rest /= 9;
    int par  = rest & 1;

    int r = lane >> 2, c = (lane & 3) * 2;
    int o  = mt * 16 + r + ((q & 1) ? 8 : 0);
    int ch = c + ((q & 2) ? 8 : 0);
    int i = tap / 3, j = tap % 3;

    uint32_t packed = 0;
#pragma unroll
    for (int hp = 0; hp < 2; hp++) {
        int cg = 2 * (k2 * 16 + ch + hp) + par;      // global channel
        float v = Wt[(size_t)o * 576 + cg * 9 + j * 3 + i];
        packed |= (uint32_t)__half_as_ushort(__float2half(v)) << (hp * 16);
    }
    g_wfrag[e] = packed;
}

// ------------------------------------------------------------------
// PTX helpers
// ------------------------------------------------------------------
__device__ __forceinline__ uint32_t smem_to_u32(const void* p) {
    uint32_t a;
    asm("{ .reg .u64 t; cvta.to.shared.u64 t, %1; cvt.u32.u64 %0, t; }"
        : "=r"(a) : "l"(p));
    return a;
}
__device__ __forceinline__ void ldsm4(uint32_t* r, uint32_t addr) {
    asm volatile("ldmatrix.sync.aligned.m8n8.x4.shared.b16 {%0,%1,%2,%3}, [%4];"
                 : "=r"(r[0]), "=r"(r[1]), "=r"(r[2]), "=r"(r[3]) : "r"(addr));
}
__device__ __forceinline__ void mma16816(float* d, const uint4 a,
                                         uint32_t b0, uint32_t b1) {
    asm volatile("mma.sync.aligned.m16n8k16.row.col.f32.f16.f16.f32 "
                 "{%0,%1,%2,%3}, {%4,%5,%6,%7}, {%8,%9}, {%0,%1,%2,%3};"
                 : "+f"(d[0]), "+f"(d[1]), "+f"(d[2]), "+f"(d[3])
                 : "r"(a.x), "r"(a.y), "r"(a.z), "r"(a.w), "r"(b0), "r"(b1));
}

// smem: X fp16, 10 rows * 18 cols * 128B
#define SMEM_TOTAL 23040

// ------------------------------------------------------------------
// Main kernel: CTA = batch b, 8 output rows x 16 cols. M=64 (o), N=128 (pix).
// Warp wid owns output row s=wid. Weights from g_wfrag via LDG (L1-hot).
// X tile copied from pre-packed g_xh rows (16B-chunk XOR permute only).
// ------------------------------------------------------------------
__global__ void __launch_bounds__(256, 2)
conv_mma_kernel(const float* __restrict__ bias,
                float* __restrict__ out) {
    extern __shared__ __align__(16) unsigned char smem[];
    const uint32_t sb32 = smem_to_u32(smem);

    const int tid = threadIdx.x;
    const int wid = tid >> 5;
    const int lid = tid & 31;
    const int b  = blockIdx.z;
    const int h0 = blockIdx.y * 8;
    const int w0 = blockIdx.x * 16;

    // ---- fill X tile: 180 position-rows x 8 chunks of 16B ----
    const unsigned char* xbase_g = g_xh + ((size_t)b << 12) * 128;
    for (int idx = tid; idx < 1440; idx += 256) {
        int chunk = idx & 7;
        int pos   = idx >> 3;
        int r  = pos / 18;
        int cl = pos - r * 18;
        int hin = min(max(h0 + r  - 1, 0), 63);
        int win = min(max(w0 + cl - 1, 0), 63);
        uint4 v = *(const uint4*)(xbase_g + ((size_t)(hin * 64 + win)) * 128 + chunk * 16);
        *(uint4*)(smem + r * 2304 + cl * 128 + ((chunk ^ (cl & 7)) << 4)) = v;
    }
    __syncthreads();

    // ---- mainloop ----
    const int lm = lid & 15, kh = lid >> 4;

    uint32_t rowb[3], colj[3], swzj[3];
#pragma unroll
    for (int i = 0; i < 3; i++) rowb[i] = (uint32_t)((wid + i) * 2304);
#pragma unroll
    for (int j = 0; j < 3; j++) {
        int cB = lm + j;
        colj[j] = (uint32_t)(cB * 128);
        swzj[j] = (uint32_t)((cB & 7) << 4);
    }
    const uint32_t kh16 = (uint32_t)(kh * 16);

    float accE[32], accO[32];
#pragma unroll
    for (int i = 0; i < 32; i++) { accE[i] = 0.f; accO[i] = 0.f; }

    const uint4* __restrict__ wf = reinterpret_cast<const uint4*>(g_wfrag);

    auto gemm_par = [&](float (&acc)[32], int par) {
        const uint4* wsp = wf + (size_t)(par * 9) * 256 + lid;
        const uint32_t parq = (uint32_t)(par * 64) + kh16;
#pragma unroll
        for (int tap = 0; tap < 9; tap++) {
            const int i = tap / 3, j = tap % 3;
            const uint32_t xrow = sb32 + rowb[i] + colj[j];
            const uint32_t bin0 = parq ^ swzj[j];
            const uint4* wtap = wsp + tap * 256;
#pragma unroll
            for (int k2 = 0; k2 < 2; k2++) {
                uint32_t bb[4];
                ldsm4(bb, xrow + (bin0 ^ (uint32_t)(k2 << 5)));
                const uint4* wk = wtap + k2 * 128;
                uint4 a0 = wk[0];
                uint4 a1 = wk[32];
                uint4 a2 = wk[64];
                uint4 a3 = wk[96];
                mma16816(acc + 0,  a0, bb[0], bb[2]);
                mma16816(acc + 4,  a0, bb[1], bb[3]);
                mma16816(acc + 8,  a1, bb[0], bb[2]);
                mma16816(acc + 12, a1, bb[1], bb[3]);
                mma16816(acc + 16, a2, bb[0], bb[2]);
                mma16816(acc + 20, a2, bb[1], bb[3]);
                mma16816(acc + 24, a3, bb[0], bb[2]);
                mma16816(acc + 28, a3, bb[1], bb[3]);
            }
        }
    };

    gemm_par(accE, 0);
    gemm_par(accO, 1);

    // ---- epilogue ----
    const int g = lid >> 2, t4 = lid & 3;
    const int hrow = h0 + wid;
    float i0[2][2], i1[2][2], sc0[2][2], sc1[2][2];
#pragma unroll
    for (int nt = 0; nt < 2; nt++) {
        int wloc = nt * 8 + 2 * t4;
        int sidx = b * HW_ + hrow * 64 + (w0 + wloc);
#pragma unroll
        for (int e = 0; e < 2; e++) {
            float a0v = g_s0[sidx + e], a1v = g_s1[sidx + e];
            sc0[nt][e] = a0v; sc1[nt][e] = a1v;
            i0[nt][e] = 1.0f / a0v; i1[nt][e] = 1.0f / a1v;
        }
    }
#pragma unroll
    for (int mt = 0; mt < 4; mt++) {
#pragma unroll
        for (int half = 0; half < 2; half++) {
            int o = mt * 16 + g + half * 8;
            float bo = bias[o];
            bool odd = (o & 1) != 0;
#pragma unroll
            for (int nt = 0; nt < 2; nt++) {
                float2 vv;
                float* pv = &vv.x;
#pragma unroll
                for (int e = 0; e < 2; e++) {
                    int k = (mt * 2 + nt) * 4 + half * 2 + e;
                    float v = accE[k] * i0[nt][e] + accO[k] * i1[nt][e] + bo;
                    v = (v >= 0.f) ? v : (SLOPE * v);
                    v *= odd ? sc1[nt][e] : sc0[nt][e];
                    pv[e] = v;
                }
                int wloc = nt * 8 + 2 * t4;
                *reinterpret_cast<float2*>(
                    out + ((size_t)(b * O_ + o) * HW_) + hrow * 64 + w0 + wloc) = vv;
            }
        }
    }
}

// ------------------------------------------------------------------
extern "C" void kernel_launch(void* const* d_in, const int* in_sizes, int n_in,
                              void* d_out, int out_size) {
    const float* x    = (const float*)d_in[0];
    const float* Wt   = (const float*)d_in[1];
    const float* bias = (const float*)d_in[2];
    float* out = (float*)d_out;

    cudaFuncSetAttribute(conv_mma_kernel,
                         cudaFuncAttributeMaxDynamicSharedMemorySize, SMEM_TOTAL);

    dim3 pgrid(HW_ / 64, B_);                 // (64, 16)
    chan_pack_kernel<<<pgrid, 256>>>(x);
    window_std_kernel<<<(B_ * HW_) / 256, 256>>>();
    wprep_kernel<<<72, 256>>>(Wt);

    dim3 grid(4, 8, 16);   // wtiles, htiles, batch
    conv_mma_kernel<<<grid, 256, SMEM_TOTAL>>>(bias, out);
}

// round 10
// speedup vs baseline: 6.5341x; 1.2757x over previous
#include <cuda_runtime.h>
#include <cuda_fp16.h>
#include <cstdint>

#define B_  16
#define C_  64
#define O_  64
#define H_  64
#define Wd_ 64
#define HW_ (H_ * Wd_)
#define EPSF 1e-6f
#define SLOPE 0.01f

// ---- scratch ----
__device__ float g_cmax0[B_ * HW_];
__device__ float g_cmin0[B_ * HW_];
__device__ float g_cmax1[B_ * HW_];
__device__ float g_cmin1[B_ * HW_];
// per-lane A-fragment image: [par][tap][k2][mt][lane][4 u32] = 18432 u32 (fp16x2)
__device__ __align__(16) uint32_t g_wfrag[18432];
// NHWC-permuted fp16 x: [b][h][w][cperm] — 128 B per pixel
__device__ __align__(16) unsigned char g_xh[B_ * HW_ * 128];

// ------------------------------------------------------------------
// Kernel 1 (fused): per-pixel channel min/max by parity + NHWC fp16 pack.
// ------------------------------------------------------------------
__global__ void __launch_bounds__(256)
chan_pack_kernel(const float* __restrict__ x) {
    __shared__ unsigned char stage[8192];     // 64 px * 128 B
    __shared__ float s_mx[4][64], s_mn[4][64];

    const int tid = threadIdx.x;
    const int c4 = tid >> 6;
    const int px = tid & 63;
    const int b   = blockIdx.y;
    const int px0 = blockIdx.x * 64;

    const float* xb = x + (size_t)b * C_ * HW_ + px0 + px;
    float mx = -1e30f, mn = 1e30f;
#pragma unroll
    for (int k = 0; k < 16; k++) {
        int ch = c4 + 4 * k;
        float v = xb[(size_t)ch * HW_];
        mx = fmaxf(mx, v); mn = fminf(mn, v);
        int par = ch & 1, kk = ch >> 1;
        int k2 = kk >> 4, ch16 = kk & 15;
        int kh = ch16 >> 3, chlo = ch16 & 7;
        int chunk = par * 4 + k2 * 2 + kh;
        int soff = px * 128 + ((chunk ^ (px & 7)) << 4) + chlo * 2;
        *(uint16_t*)(stage + soff) = __half_as_ushort(__float2half(v));
    }
    s_mx[c4][px] = mx; s_mn[c4][px] = mn;
    __syncthreads();

    if (tid < 64) {
        int gi = b * HW_ + px0 + tid;
        g_cmax0[gi] = fmaxf(s_mx[0][tid], s_mx[2][tid]);
        g_cmin0[gi] = fminf(s_mn[0][tid], s_mn[2][tid]);
        g_cmax1[gi] = fmaxf(s_mx[1][tid], s_mx[3][tid]);
        g_cmin1[gi] = fminf(s_mn[1][tid], s_mn[3][tid]);
    }

    unsigned char* dstb = g_xh + ((size_t)(b * HW_ + px0)) * 128;
#pragma unroll
    for (int t = 0; t < 2; t++) {
        int ci = tid * 2 + t;
        int row = ci >> 3, chunk = ci & 7;
        uint4 v = *(const uint4*)(stage + row * 128 + ((chunk ^ (row & 7)) << 4));
        *(uint4*)(dstb + row * 128 + chunk * 16) = v;
    }
}

// ------------------------------------------------------------------
// Kernel 2: weight prep -> per-lane fp16 mma A fragments (m16n8k16 layout).
// ------------------------------------------------------------------
__global__ void wprep_kernel(const float* __restrict__ Wt) {
    int e = blockIdx.x * blockDim.x + threadIdx.x;
    if (e >= 18432) return;
    int q    = e & 3;
    int lane = (e >> 2) & 31;
    int mt   = (e >> 7) & 3;
    int rest = e >> 9;
    int k2   = rest & 1;  rest >>= 1;
    int tap  = rest % 9;  rest /= 9;
    int par  = rest & 1;

    int r = lane >> 2, c = (lane & 3) * 2;
    int o  = mt * 16 + r + ((q & 1) ? 8 : 0);
    int ch = c + ((q & 2) ? 8 : 0);
    int i = tap / 3, j = tap % 3;

    uint32_t packed = 0;
#pragma unroll
    for (int hp = 0; hp < 2; hp++) {
        int cg = 2 * (k2 * 16 + ch + hp) + par;
        float v = Wt[(size_t)o * 576 + cg * 9 + j * 3 + i];
        packed |= (uint32_t)__half_as_ushort(__float2half(v)) << (hp * 16);
    }
    g_wfrag[e] = packed;
}

// ------------------------------------------------------------------
// PTX helpers
// ------------------------------------------------------------------
__device__ __forceinline__ uint32_t smem_to_u32(const void* p) {
    uint32_t a;
    asm("{ .reg .u64 t; cvta.to.shared.u64 t, %1; cvt.u32.u64 %0, t; }"
        : "=r"(a) : "l"(p));
    return a;
}
__device__ __forceinline__ void ldsm4(uint32_t* r, uint32_t addr) {
    asm volatile("ldmatrix.sync.aligned.m8n8.x4.shared.b16 {%0,%1,%2,%3}, [%4];"
                 : "=r"(r[0]), "=r"(r[1]), "=r"(r[2]), "=r"(r[3]) : "r"(addr));
}
__device__ __forceinline__ void mma16816(float* d, const uint4 a,
                                         uint32_t b0, uint32_t b1) {
    asm volatile("mma.sync.aligned.m16n8k16.row.col.f32.f16.f16.f32 "
                 "{%0,%1,%2,%3}, {%4,%5,%6,%7}, {%8,%9}, {%0,%1,%2,%3};"
                 : "+f"(d[0]), "+f"(d[1]), "+f"(d[2]), "+f"(d[3])
                 : "r"(a.x), "r"(a.y), "r"(a.z), "r"(a.w), "r"(b0), "r"(b1));
}
__device__ __forceinline__ void cpasync16(uint32_t dst, const void* src) {
    asm volatile("cp.async.ca.shared.global [%0], [%1], 16;"
                 :: "r"(dst), "l"(src) : "memory");
}

// smem: X fp16 (10*18*128 = 23040), s0 tile (512B), s1 tile (512B)
#define SOFF0 23040
#define SOFF1 23552
#define SMEM_TOTAL 24064

// ------------------------------------------------------------------
// Main kernel: CTA = batch b, 8 output rows x 16 cols. M=64 (o), N=128 (pix).
// Prologue also computes s0/s1 for the tile (window minmax) into smem.
// ------------------------------------------------------------------
__global__ void __launch_bounds__(256, 2)
conv_mma_kernel(const float* __restrict__ bias,
                float* __restrict__ out) {
    extern __shared__ __align__(16) unsigned char smem[];
    const uint32_t sb32 = smem_to_u32(smem);
    float* s0s = reinterpret_cast<float*>(smem + SOFF0);
    float* s1s = reinterpret_cast<float*>(smem + SOFF1);

    const int tid = threadIdx.x;
    const int wid = tid >> 5;
    const int lid = tid & 31;
    const int b  = blockIdx.z;
    const int h0 = blockIdx.y * 8;
    const int w0 = blockIdx.x * 16;

    // ---- async fill of X tile: 180 position-rows x 8 chunks of 16B ----
    const unsigned char* xbase_g = g_xh + ((size_t)b << 12) * 128;
    for (int idx = tid; idx < 1440; idx += 256) {
        int chunk = idx & 7;
        int pos   = idx >> 3;
        int r  = pos / 18;
        int cl = pos - r * 18;
        int hin = min(max(h0 + r  - 1, 0), 63);
        int win = min(max(w0 + cl - 1, 0), 63);
        cpasync16(sb32 + r * 2304 + cl * 128 + ((chunk ^ (cl & 7)) << 4),
                  xbase_g + ((size_t)(hin * 64 + win)) * 128 + chunk * 16);
    }
    asm volatile("cp.async.commit_group;" ::: "memory");

    // ---- compute s0/s1 for the 8x16 tile (overlaps the async fill) ----
    if (tid < 128) {
        int srow = tid >> 4, wloc = tid & 15;
        int h = h0 + srow, w = w0 + wloc;
        int base = b * HW_;
        float mx0 = -1e30f, mn0 = 1e30f, mx1 = -1e30f, mn1 = 1e30f;
#pragma unroll
        for (int di = -1; di <= 1; di++)
#pragma unroll
            for (int dj = -1; dj <= 1; dj++) {
                int hh = min(max(h + di, 0), 63);
                int ww = min(max(w + dj, 0), 63);
                int idx = base + hh * 64 + ww;
                mx0 = fmaxf(mx0, g_cmax0[idx]); mn0 = fminf(mn0, g_cmin0[idx]);
                mx1 = fmaxf(mx1, g_cmax1[idx]); mn1 = fminf(mn1, g_cmin1[idx]);
            }
        s0s[tid] = (mx0 - mn0) + EPSF;
        s1s[tid] = (mx1 - mn1) + EPSF;
    }
    asm volatile("cp.async.wait_group 0;" ::: "memory");
    __syncthreads();

    // ---- mainloop ----
    const int lm = lid & 15, kh = lid >> 4;

    uint32_t rowb[3], colj[3], swzj[3];
#pragma unroll
    for (int i = 0; i < 3; i++) rowb[i] = (uint32_t)((wid + i) * 2304);
#pragma unroll
    for (int j = 0; j < 3; j++) {
        int cB = lm + j;
        colj[j] = (uint32_t)(cB * 128);
        swzj[j] = (uint32_t)((cB & 7) << 4);
    }
    const uint32_t kh16 = (uint32_t)(kh * 16);

    float accE[32], accO[32];
#pragma unroll
    for (int i = 0; i < 32; i++) { accE[i] = 0.f; accO[i] = 0.f; }

    const uint4* __restrict__ wf = reinterpret_cast<const uint4*>(g_wfrag);

    auto gemm_par = [&](float (&acc)[32], int par) {
        const uint4* wsp = wf + (size_t)(par * 9) * 256 + lid;
        const uint32_t parq = (uint32_t)(par * 64) + kh16;
#pragma unroll
        for (int tap = 0; tap < 9; tap++) {
            const int i = tap / 3, j = tap % 3;
            const uint32_t xrow = sb32 + rowb[i] + colj[j];
            const uint32_t bin0 = parq ^ swzj[j];
            const uint4* wtap = wsp + tap * 256;
#pragma unroll
            for (int k2 = 0; k2 < 2; k2++) {
                uint32_t bb[4];
                ldsm4(bb, xrow + (bin0 ^ (uint32_t)(k2 << 5)));
                const uint4* wk = wtap + k2 * 128;
                uint4 a0 = wk[0];
                uint4 a1 = wk[32];
                uint4 a2 = wk[64];
                uint4 a3 = wk[96];
                mma16816(acc + 0,  a0, bb[0], bb[2]);
                mma16816(acc + 4,  a0, bb[1], bb[3]);
                mma16816(acc + 8,  a1, bb[0], bb[2]);
                mma16816(acc + 12, a1, bb[1], bb[3]);
                mma16816(acc + 16, a2, bb[0], bb[2]);
                mma16816(acc + 20, a2, bb[1], bb[3]);
                mma16816(acc + 24, a3, bb[0], bb[2]);
                mma16816(acc + 28, a3, bb[1], bb[3]);
            }
        }
    };

    gemm_par(accE, 0);
    gemm_par(accO, 1);

    // ---- epilogue ----
    const int g = lid >> 2, t4 = lid & 3;
    const int hrow = h0 + wid;
    float i0[2][2], i1[2][2], sc0[2][2], sc1[2][2];
#pragma unroll
    for (int nt = 0; nt < 2; nt++) {
        int wloc = nt * 8 + 2 * t4;
#pragma unroll
        for (int e = 0; e < 2; e++) {
            float a0v = s0s[wid * 16 + wloc + e];
            float a1v = s1s[wid * 16 + wloc + e];
            sc0[nt][e] = a0v; sc1[nt][e] = a1v;
            i0[nt][e] = 1.0f / a0v; i1[nt][e] = 1.0f / a1v;
        }
    }
#pragma unroll
    for (int mt = 0; mt < 4; mt++) {
#pragma unroll
        for (int half = 0; half < 2; half++) {
            int o = mt * 16 + g + half * 8;
            float bo = bias[o];
            bool odd = (o & 1) != 0;
#pragma unroll
            for (int nt = 0; nt < 2; nt++) {
                float2 vv;
                float* pv = &vv.x;
#pragma unroll
                for (int e = 0; e < 2; e++) {
                    int k = (mt * 2 + nt) * 4 + half * 2 + e;
                    float v = accE[k] * i0[nt][e] + accO[k] * i1[nt][e] + bo;
                    v = (v >= 0.f) ? v : (SLOPE * v);
                    v *= odd ? sc1[nt][e] : sc0[nt][e];
                    pv[e] = v;
                }
                int wloc = nt * 8 + 2 * t4;
                *reinterpret_cast<float2*>(
                    out + ((size_t)(b * O_ + o) * HW_) + hrow * 64 + w0 + wloc) = vv;
            }
        }
    }
}

// ------------------------------------------------------------------
extern "C" void kernel_launch(void* const* d_in, const int* in_sizes, int n_in,
                              void* d_out, int out_size) {
    const float* x    = (const float*)d_in[0];
    const float* Wt   = (const float*)d_in[1];
    const float* bias = (const float*)d_in[2];
    float* out = (float*)d_out;

    cudaFuncSetAttribute(conv_mma_kernel,
                         cudaFuncAttributeMaxDynamicSharedMemorySize, SMEM_TOTAL);

    dim3 pgrid(HW_ / 64, B_);                 // (64, 16)
    chan_pack_kernel<<<pgrid, 256>>>(x);
    wprep_kernel<<<72, 256>>>(Wt);

    dim3 grid(4, 8, 16);   // wtiles, htiles, batch
    conv_mma_kernel<<<grid, 256, SMEM_TOTAL>>>(bias, out);
}

// round 13
// speedup vs baseline: 7.0505x; 1.0790x over previous
#include <cuda_runtime.h>
#include <cuda_fp16.h>
#include <cstdint>

#define B_  16
#define C_  64
#define O_  64
#define H_  64
#define Wd_ 64
#define HW_ (H_ * Wd_)
#define EPSF 1e-6f
#define SLOPE 0.01f

// ---- scratch ----
__device__ float g_cmax0[B_ * HW_];
__device__ float g_cmin0[B_ * HW_];
__device__ float g_cmax1[B_ * HW_];
__device__ float g_cmin1[B_ * HW_];
// per-lane A-fragment image: [par][tap][k2][mt][lane][4 u32] = 18432 u32 (fp16x2)
__device__ __align__(16) uint32_t g_wfrag[18432];
// NHWC-permuted fp16 x: [b][h][w][cperm] — 128 B per pixel
__device__ __align__(16) unsigned char g_xh[B_ * HW_ * 128];

// ------------------------------------------------------------------
// Kernel 1 (fused): per-pixel channel min/max by parity + NHWC fp16 pack.
// Block: 256 pixels. Thread: c4 = tid>>6 -> (par = c4&1, k2 = c4>>1),
// pxg = tid&63 -> pixels pxg*4 .. pxg*4+3 (float4 loads over pixels).
// Each thread builds whole 16B chunks -> STS.128.
// ------------------------------------------------------------------
__global__ void __launch_bounds__(256)
chan_pack_kernel(const float* __restrict__ x) {
    __shared__ unsigned char stage[32768];        // 256 px * 128 B
    __shared__ float4 s_mx4[4][64], s_mn4[4][64];

    const int tid = threadIdx.x;
    const int c4  = tid >> 6;
    const int pxg = tid & 63;
    const int par = c4 & 1, k2 = c4 >> 1;
    const int b   = blockIdx.y;
    const int px0 = blockIdx.x * 256;

    const float* xb = x + (size_t)b * C_ * HW_ + px0 + pxg * 4;

    float4 v[8][2];
    float4 mx = make_float4(-1e30f, -1e30f, -1e30f, -1e30f);
    float4 mn = make_float4( 1e30f,  1e30f,  1e30f,  1e30f);
#pragma unroll
    for (int m = 0; m < 8; m++)
#pragma unroll
        for (int t = 0; t < 2; t++) {
            int kk = k2 * 16 + 2 * m + t;
            int ch = 2 * kk + par;
            float4 vv = *reinterpret_cast<const float4*>(xb + (size_t)ch * HW_);
            v[m][t] = vv;
            mx.x = fmaxf(mx.x, vv.x); mn.x = fminf(mn.x, vv.x);
            mx.y = fmaxf(mx.y, vv.y); mn.y = fminf(mn.y, vv.y);
            mx.z = fmaxf(mx.z, vv.z); mn.z = fminf(mn.z, vv.z);
            mx.w = fmaxf(mx.w, vv.w); mn.w = fminf(mn.w, vv.w);
        }
    s_mx4[c4][pxg] = mx; s_mn4[c4][pxg] = mn;

    // ---- pack: per pixel e, per kh: uint4 chunk from 8 chlo values ----
#pragma unroll
    for (int e = 0; e < 4; e++) {
        int px = pxg * 4 + e;
        int sw = (pxg & 7);
#pragma unroll
        for (int khh = 0; khh < 2; khh++) {
            uint32_t q[4];
#pragma unroll
            for (int p = 0; p < 4; p++) {
                int m = khh * 4 + p;
                const float* f0 = &v[m][0].x;
                const float* f1 = &v[m][1].x;
                __half2 h2 = __floats2half2_rn(f0[e], f1[e]);
                q[p] = *reinterpret_cast<uint32_t*>(&h2);
            }
            int chunk = par * 4 + k2 * 2 + khh;
            uint4 u = make_uint4(q[0], q[1], q[2], q[3]);
            *reinterpret_cast<uint4*>(stage + px * 128 + ((chunk ^ sw) << 4)) = u;
        }
    }
    __syncthreads();

    // ---- minmax combine + write (float4 over pixels) ----
    if (tid < 64) {
        int gi4 = (b * HW_ + px0) / 4 + tid;
        float4 a, c, r;
        a = s_mx4[0][tid]; c = s_mx4[2][tid];
        r = make_float4(fmaxf(a.x,c.x), fmaxf(a.y,c.y), fmaxf(a.z,c.z), fmaxf(a.w,c.w));
        reinterpret_cast<float4*>(g_cmax0)[gi4] = r;
        a = s_mn4[0][tid]; c = s_mn4[2][tid];
        r = make_float4(fminf(a.x,c.x), fminf(a.y,c.y), fminf(a.z,c.z), fminf(a.w,c.w));
        reinterpret_cast<float4*>(g_cmin0)[gi4] = r;
        a = s_mx4[1][tid]; c = s_mx4[3][tid];
        r = make_float4(fmaxf(a.x,c.x), fmaxf(a.y,c.y), fmaxf(a.z,c.z), fmaxf(a.w,c.w));
        reinterpret_cast<float4*>(g_cmax1)[gi4] = r;
        a = s_mn4[1][tid]; c = s_mn4[3][tid];
        r = make_float4(fminf(a.x,c.x), fminf(a.y,c.y), fminf(a.z,c.z), fminf(a.w,c.w));
        reinterpret_cast<float4*>(g_cmin1)[gi4] = r;
    }

    // ---- copy stage -> g_xh (linear chunks) ----
    unsigned char* dstb = g_xh + ((size_t)(b * HW_ + px0)) * 128;
#pragma unroll
    for (int t2 = 0; t2 < 8; t2++) {
        int ci = tid + 256 * t2;
        int row = ci >> 3, chunk = ci & 7;
        uint4 u = *reinterpret_cast<const uint4*>(
            stage + row * 128 + ((chunk ^ ((row >> 2) & 7)) << 4));
        *reinterpret_cast<uint4*>(dstb + row * 128 + chunk * 16) = u;
    }
}

// ------------------------------------------------------------------
// Kernel 2: weight prep -> per-lane fp16 mma A fragments (m16n8k16 layout).
// ------------------------------------------------------------------
__global__ void wprep_kernel(const float* __restrict__ Wt) {
    int e = blockIdx.x * blockDim.x + threadIdx.x;
    if (e >= 18432) return;
    int q    = e & 3;
    int lane = (e >> 2) & 31;
    int mt   = (e >> 7) & 3;
    int rest = e >> 9;
    int k2   = rest & 1;  rest >>= 1;
    int tap  = rest % 9;  rest /= 9;
    int par  = rest & 1;

    int r = lane >> 2, c = (lane & 3) * 2;
    int o  = mt * 16 + r + ((q & 1) ? 8 : 0);
    int ch = c + ((q & 2) ? 8 : 0);
    int i = tap / 3, j = tap % 3;

    uint32_t packed = 0;
#pragma unroll
    for (int hp = 0; hp < 2; hp++) {
        int cg = 2 * (k2 * 16 + ch + hp) + par;
        float v = Wt[(size_t)o * 576 + cg * 9 + j * 3 + i];
        packed |= (uint32_t)__half_as_ushort(__float2half(v)) << (hp * 16);
    }
    g_wfrag[e] = packed;
}

// ------------------------------------------------------------------
// PTX helpers
// ------------------------------------------------------------------
__device__ __forceinline__ uint32_t smem_to_u32(const void* p) {
    uint32_t a;
    asm("{ .reg .u64 t; cvta.to.shared.u64 t, %1; cvt.u32.u64 %0, t; }"
        : "=r"(a) : "l"(p));
    return a;
}
__device__ __forceinline__ void ldsm4(uint32_t* r, uint32_t addr) {
    asm volatile("ldmatrix.sync.aligned.m8n8.x4.shared.b16 {%0,%1,%2,%3}, [%4];"
                 : "=r"(r[0]), "=r"(r[1]), "=r"(r[2]), "=r"(r[3]) : "r"(addr));
}
__device__ __forceinline__ void mma16816(float* d, const uint4 a,
                                         uint32_t b0, uint32_t b1) {
    asm volatile("mma.sync.aligned.m16n8k16.row.col.f32.f16.f16.f32 "
                 "{%0,%1,%2,%3}, {%4,%5,%6,%7}, {%8,%9}, {%0,%1,%2,%3};"
                 : "+f"(d[0]), "+f"(d[1]), "+f"(d[2]), "+f"(d[3])
                 : "r"(a.x), "r"(a.y), "r"(a.z), "r"(a.w), "r"(b0), "r"(b1));
}
__device__ __forceinline__ void cpasync16(uint32_t dst, const void* src) {
    asm volatile("cp.async.ca.shared.global [%0], [%1], 16;"
                 :: "r"(dst), "l"(src) : "memory");
}

// smem: X buffers (2 x 23040), s0[2][128], s1[2][128]
#define XBUF   23040
#define SOFF0  46080
#define SOFF1  47104
#define SMEM_TOTAL 48128

// ------------------------------------------------------------------
// Main kernel: CTA = batch b, 8 rows x 32 cols as TWO 8x16 tiles,
// double-buffered cp.async. Grid 256 = one wave at 2 CTAs/SM.
// ------------------------------------------------------------------
__global__ void __launch_bounds__(256, 2)
conv_mma_kernel(const float* __restrict__ bias,
                float* __restrict__ out) {
    extern __shared__ __align__(16) unsigned char smem[];
    const uint32_t sb32 = smem_to_u32(smem);
    float* s0s = reinterpret_cast<float*>(smem + SOFF0);
    float* s1s = reinterpret_cast<float*>(smem + SOFF1);

    const int tid = threadIdx.x;
    const int wid = tid >> 5;
    const int lid = tid & 31;
    const int b  = blockIdx.z;
    const int h0 = blockIdx.y * 8;
    const int wb = blockIdx.x * 32;

    const unsigned char* xbase_g = g_xh + ((size_t)b << 12) * 128;

    // ---- fill tile 0 (async) ----
#pragma unroll 1
    for (int idx = tid; idx < 1440; idx += 256) {
        int chunk = idx & 7;
        int pos   = idx >> 3;
        int r  = pos / 18;
        int cl = pos - r * 18;
        int hin = min(max(h0 + r  - 1, 0), 63);
        int win = min(max(wb + cl - 1, 0), 63);
        cpasync16(sb32 + r * 2304 + cl * 128 + ((chunk ^ (cl & 7)) << 4),
                  xbase_g + ((size_t)(hin * 64 + win)) * 128 + chunk * 16);
    }
    asm volatile("cp.async.commit_group;" ::: "memory");

    // ---- compute s0/s1 for BOTH tiles (overlaps fills) ----
    {
        int tile = tid >> 7;            // 0 or 1
        int lt   = tid & 127;
        int srow = lt >> 4, wloc = lt & 15;
        int h = h0 + srow, w = wb + tile * 16 + wloc;
        int base = b * HW_;
        float mx0 = -1e30f, mn0 = 1e30f, mx1 = -1e30f, mn1 = 1e30f;
#pragma unroll
        for (int di = -1; di <= 1; di++)
#pragma unroll
            for (int dj = -1; dj <= 1; dj++) {
                int hh = min(max(h + di, 0), 63);
                int ww = min(max(w + dj, 0), 63);
                int idx = base + hh * 64 + ww;
                mx0 = fmaxf(mx0, g_cmax0[idx]); mn0 = fminf(mn0, g_cmin0[idx]);
                mx1 = fmaxf(mx1, g_cmax1[idx]); mn1 = fminf(mn1, g_cmin1[idx]);
            }
        s0s[tid] = (mx0 - mn0) + EPSF;
        s1s[tid] = (mx1 - mn1) + EPSF;
    }

    // ---- fill tile 1 (async, second group) ----
#pragma unroll 1
    for (int idx = tid; idx < 1440; idx += 256) {
        int chunk = idx & 7;
        int pos   = idx >> 3;
        int r  = pos / 18;
        int cl = pos - r * 18;
        int hin = min(max(h0 + r  - 1, 0), 63);
        int win = min(max(wb + 16 + cl - 1, 0), 63);
        cpasync16(sb32 + XBUF + r * 2304 + cl * 128 + ((chunk ^ (cl & 7)) << 4),
                  xbase_g + ((size_t)(hin * 64 + win)) * 128 + chunk * 16);
    }
    asm volatile("cp.async.commit_group;" ::: "memory");
    asm volatile("cp.async.wait_group 1;" ::: "memory");   // tile-0 ready
    __syncthreads();

    // ---- hoisted per-lane constants ----
    const int lm = lid & 15, kh = lid >> 4;
    uint32_t rowb[3], colj[3], swzj[3];
#pragma unroll
    for (int i = 0; i < 3; i++) rowb[i] = (uint32_t)((wid + i) * 2304);
#pragma unroll
    for (int j = 0; j < 3; j++) {
        int cB = lm + j;
        colj[j] = (uint32_t)(cB * 128);
        swzj[j] = (uint32_t)((cB & 7) << 4);
    }
    const uint32_t kh16 = (uint32_t)(kh * 16);
    const uint4* __restrict__ wf = reinterpret_cast<const uint4*>(g_wfrag);
    const int g = lid >> 2, t4 = lid & 3;
    const int hrow = h0 + wid;

#pragma unroll 1
    for (int tile = 0; tile < 2; tile++) {
        const uint32_t xb32 = sb32 + tile * XBUF;
        const int w0 = wb + tile * 16;

        float accE[32], accO[32];
#pragma unroll
        for (int i = 0; i < 32; i++) { accE[i] = 0.f; accO[i] = 0.f; }

        auto gemm_par = [&](float (&acc)[32], int par) {
            const uint4* wsp = wf + (size_t)(par * 9) * 256 + lid;
            const uint32_t parq = (uint32_t)(par * 64) + kh16;
#pragma unroll
            for (int tap = 0; tap < 9; tap++) {
                const int i = tap / 3, j = tap % 3;
                const uint32_t xrow = xb32 + rowb[i] + colj[j];
                const uint32_t bin0 = parq ^ swzj[j];
                const uint4* wtap = wsp + tap * 256;
#pragma unroll
                for (int k2 = 0; k2 < 2; k2++) {
                    uint32_t bb[4];
                    ldsm4(bb, xrow + (bin0 ^ (uint32_t)(k2 << 5)));
                    const uint4* wk = wtap + k2 * 128;
                    uint4 a0 = wk[0];
                    uint4 a1 = wk[32];
                    uint4 a2 = wk[64];
                    uint4 a3 = wk[96];
                    mma16816(acc + 0,  a0, bb[0], bb[2]);
                    mma16816(acc + 4,  a0, bb[1], bb[3]);
                    mma16816(acc + 8,  a1, bb[0], bb[2]);
                    mma16816(acc + 12, a1, bb[1], bb[3]);
                    mma16816(acc + 16, a2, bb[0], bb[2]);
                    mma16816(acc + 20, a2, bb[1], bb[3]);
                    mma16816(acc + 24, a3, bb[0], bb[2]);
                    mma16816(acc + 28, a3, bb[1], bb[3]);
                }
            }
        };

        gemm_par(accE, 0);
        gemm_par(accO, 1);

        // ---- epilogue ----
        float i0[2][2], i1[2][2], sc0[2][2], sc1[2][2];
#pragma unroll
        for (int nt = 0; nt < 2; nt++) {
            int wloc = nt * 8 + 2 * t4;
#pragma unroll
            for (int e = 0; e < 2; e++) {
                float a0v = s0s[tile * 128 + wid * 16 + wloc + e];
                float a1v = s1s[tile * 128 + wid * 16 + wloc + e];
                sc0[nt][e] = a0v; sc1[nt][e] = a1v;
                i0[nt][e] = 1.0f / a0v; i1[nt][e] = 1.0f / a1v;
            }
        }
#pragma unroll
        for (int mt = 0; mt < 4; mt++) {
#pragma unroll
            for (int half = 0; half < 2; half++) {
                int o = mt * 16 + g + half * 8;
                float bo = bias[o];
                bool odd = (o & 1) != 0;
#pragma unroll
                for (int nt = 0; nt < 2; nt++) {
                    float2 vv;
                    float* pv = &vv.x;
#pragma unroll
                    for (int e = 0; e < 2; e++) {
                        int k = (mt * 2 + nt) * 4 + half * 2 + e;
                        float v = accE[k] * i0[nt][e] + accO[k] * i1[nt][e] + bo;
                        v = (v >= 0.f) ? v : (SLOPE * v);
                        v *= odd ? sc1[nt][e] : sc0[nt][e];
                        pv[e] = v;
                    }
                    int wloc = nt * 8 + 2 * t4;
                    *reinterpret_cast<float2*>(
                        out + ((size_t)(b * O_ + o) * HW_) + hrow * 64 + w0 + wloc) = vv;
                }
            }
        }

        if (tile == 0) {
            asm volatile("cp.async.wait_group 0;" ::: "memory");   // tile-1 ready
            __syncthreads();
        }
    }
}

// ------------------------------------------------------------------
extern "C" void kernel_launch(void* const* d_in, const int* in_sizes, int n_in,
                              void* d_out, int out_size) {
    const float* x    = (const float*)d_in[0];
    const float* Wt   = (const float*)d_in[1];
    const float* bias = (const float*)d_in[2];
    float* out = (float*)d_out;

    cudaFuncSetAttribute(conv_mma_kernel,
                         cudaFuncAttributeMaxDynamicSharedMemorySize, SMEM_TOTAL);

    dim3 pgrid(HW_ / 256, B_);                // (16, 16)
    chan_pack_kernel<<<pgrid, 256>>>(x);
    wprep_kernel<<<72, 256>>>(Wt);

    dim3 grid(2, 8, 16);   // w-tile pairs, h tiles, batch
    conv_mma_kernel<<<grid, 256, SMEM_TOTAL>>>(bias, out);
}